// round 1
// baseline (speedup 1.0000x reference)
#include <cuda_runtime.h>
#include <math.h>

#define N_DRUG 572
#define D 512
#define KNBR 64
#define RREL 200
#define MAXDEG 32
#define EPS 1e-5f

// ---------------- scratch (no allocs allowed) ----------------
__device__ float g_q[N_DRUG * D];
__device__ float g_agg[N_DRUG * D];
__device__ float g_h[N_DRUG * D];
__device__ float g_psum[16 * D];
__device__ float g_psumsq[16 * D];
__device__ float g_mean[D];
__device__ float g_rstd[D];

// ---------------- k1: q = drug_e @ Wa  (8 rows x 256 cols per block) ----------------
__global__ void k_qgemm(const float* __restrict__ drugW,
                        const float* __restrict__ Wa,
                        const int* __restrict__ names) {
    const int r0 = blockIdx.x * 8;
    const int d  = blockIdx.y * 256 + threadIdx.x;
    __shared__ __align__(16) float sh[8][D];
    const int nrows = min(8, N_DRUG - r0);
    for (int idx = threadIdx.x; idx < 8 * D; idx += 256) {
        int r = idx >> 9, c = idx & (D - 1);
        float v = 0.f;
        if (r < nrows) v = drugW[(size_t)names[r0 + r] * D + c];
        sh[r][c] = v;
    }
    __syncthreads();
    float acc[8] = {0.f, 0.f, 0.f, 0.f, 0.f, 0.f, 0.f, 0.f};
    #pragma unroll 4
    for (int k = 0; k < D; k += 4) {
        float w0 = Wa[(k + 0) * D + d];
        float w1 = Wa[(k + 1) * D + d];
        float w2 = Wa[(k + 2) * D + d];
        float w3 = Wa[(k + 3) * D + d];
        #pragma unroll
        for (int r = 0; r < 8; r++) {
            float4 a = *reinterpret_cast<const float4*>(&sh[r][k]);
            acc[r] += a.x * w0 + a.y * w1 + a.z * w2 + a.w * w3;
        }
    }
    for (int r = 0; r < nrows; r++)
        g_q[(size_t)(r0 + r) * D + d] = acc[r];
}

// ---------------- k2: attention scores + softmax + gather-aggregate ----------------
__global__ void k_attn(const float* __restrict__ relaW,
                       const float* __restrict__ entW,
                       const int* __restrict__ adjR,
                       const int* __restrict__ adjT) {
    const int n = blockIdx.x;
    const int tid = threadIdx.x;           // 256 threads
    __shared__ float qsh[D];
    __shared__ float sc[KNBR];
    __shared__ float attn[KNBR];
    __shared__ int relS[KNBR], tailS[KNBR];

    if (tid < KNBR) {
        relS[tid]  = adjR[n * KNBR + tid];
        tailS[tid] = adjT[n * KNBR + tid];
    }
    qsh[tid]       = g_q[(size_t)n * D + tid];
    qsh[tid + 256] = g_q[(size_t)n * D + tid + 256];
    __syncthreads();

    const int w = tid >> 5, lane = tid & 31;
    // 8 warps, each computes 8 dot products of length 512
    #pragma unroll
    for (int kk = 0; kk < 8; kk++) {
        int k = w * 8 + kk;
        const float* base = relaW + (size_t)relS[k] * D;
        float p = 0.f;
        #pragma unroll
        for (int i = 0; i < 16; i++)
            p += qsh[lane + 32 * i] * base[lane + 32 * i];
        #pragma unroll
        for (int off = 16; off; off >>= 1)
            p += __shfl_xor_sync(0xffffffffu, p, off);
        if (lane == 0) sc[k] = p * 0.044194173824159216f;  // 1/sqrt(512)
    }
    __syncthreads();

    if (w == 0) {
        float v0 = sc[lane], v1 = sc[lane + 32];
        float m = fmaxf(v0, v1);
        #pragma unroll
        for (int off = 16; off; off >>= 1)
            m = fmaxf(m, __shfl_xor_sync(0xffffffffu, m, off));
        float e0 = expf(v0 - m), e1 = expf(v1 - m);
        float s = e0 + e1;
        #pragma unroll
        for (int off = 16; off; off >>= 1)
            s += __shfl_xor_sync(0xffffffffu, s, off);
        float inv = 1.f / s;
        attn[lane] = e0 * inv;
        attn[lane + 32] = e1 * inv;
    }
    __syncthreads();

    float a0 = 0.f, a1 = 0.f;
    const int d = tid;
    #pragma unroll 4
    for (int k = 0; k < KNBR; k++) {
        const float* er = entW + (size_t)tailS[k] * D;
        float a = attn[k];
        a0 += a * er[d];
        a1 += a * er[d + 256];
    }
    g_agg[(size_t)n * D + d]       = a0;
    g_agg[(size_t)n * D + d + 256] = a1;
}

// ---------------- k3: h = relu(concat(agg, drug_e) @ lin_W + b) ----------------
__global__ void k_lin(const float* __restrict__ drugW,
                      const float* __restrict__ linW,
                      const float* __restrict__ linb,
                      const int* __restrict__ names) {
    const int r0 = blockIdx.x * 8;
    const int d  = blockIdx.y * 256 + threadIdx.x;
    __shared__ __align__(16) float sh[8][2 * D];    // 32 KB
    const int nrows = min(8, N_DRUG - r0);
    for (int idx = threadIdx.x; idx < 8 * 2 * D; idx += 256) {
        int r = idx >> 10, c = idx & (2 * D - 1);
        float v = 0.f;
        if (r < nrows) {
            if (c < D) v = g_agg[(size_t)(r0 + r) * D + c];
            else       v = drugW[(size_t)names[r0 + r] * D + (c - D)];
        }
        sh[r][c] = v;
    }
    __syncthreads();
    float acc[8] = {0.f, 0.f, 0.f, 0.f, 0.f, 0.f, 0.f, 0.f};
    #pragma unroll 2
    for (int k = 0; k < 2 * D; k += 4) {
        float w0 = linW[(k + 0) * D + d];
        float w1 = linW[(k + 1) * D + d];
        float w2 = linW[(k + 2) * D + d];
        float w3 = linW[(k + 3) * D + d];
        #pragma unroll
        for (int r = 0; r < 8; r++) {
            float4 a = *reinterpret_cast<const float4*>(&sh[r][k]);
            acc[r] += a.x * w0 + a.y * w1 + a.z * w2 + a.w * w3;
        }
    }
    const float b = linb[d];
    for (int r = 0; r < nrows; r++) {
        float v = acc[r] + b;
        g_h[(size_t)(r0 + r) * D + d] = v > 0.f ? v : 0.f;
    }
}

// ---------------- k4: partial BN stats (16 row-slices) ----------------
__global__ void k_bnpart() {
    const int b = blockIdx.x;       // 16 blocks
    const int d = threadIdx.x;      // 512 threads
    const int r0 = b * 36;
    const int r1 = min(N_DRUG, r0 + 36);
    float s = 0.f, sq = 0.f;
    for (int r = r0; r < r1; r++) {
        float v = g_h[(size_t)r * D + d];
        s += v;
        sq += v * v;
    }
    g_psum[b * D + d] = s;
    g_psumsq[b * D + d] = sq;
}

// ---------------- k5: finalize mean/rstd ----------------
__global__ void k_bnfin() {
    const int d = threadIdx.x;
    float s = 0.f, sq = 0.f;
    #pragma unroll
    for (int b = 0; b < 16; b++) {
        s  += g_psum[b * D + d];
        sq += g_psumsq[b * D + d];
    }
    const float invN = 1.f / (float)N_DRUG;
    float mean = s * invN;
    float var = sq * invN - mean * mean;
    g_mean[d] = mean;
    g_rstd[d] = rsqrtf(var + EPS);
}

// ---------------- k6: normalize + affine -> d_out ----------------
__global__ void k_norm(const float* __restrict__ gamma,
                       const float* __restrict__ beta,
                       float* __restrict__ out) {
    const int n = blockIdx.x;
    const int d = threadIdx.x;
    float v = g_h[(size_t)n * D + d];
    out[(size_t)n * D + d] = (v - g_mean[d]) * g_rstd[d] * gamma[d] + beta[d];
}

// ---------------- k7: sequential neighbor-mean smoothing ----------------
// Column-sliced: 8 blocks, each owns 64 feature columns fully in shared memory
// (572*64 f32 = 146 KB), so the 572-step serial chain pays LDS latency, not L2.
__global__ void k_scan(float* __restrict__ out,
                       const int* __restrict__ nbrI,
                       const int* __restrict__ nbrD,
                       const int* __restrict__ epoch) {
    if (epoch[0] <= 1) return;
    extern __shared__ float fsh[];           // [572][64]
    __shared__ float red[64];
    const int tid = threadIdx.x;             // 128 threads
    const int col = tid & 63;
    const int half = tid >> 6;
    const int cbase = blockIdx.x * 64;

    for (int idx = tid; idx < N_DRUG * 64; idx += 128) {
        int r = idx >> 6, c = idx & 63;
        fsh[idx] = out[(size_t)r * D + cbase + c];
    }
    __syncthreads();

    for (int i = 0; i < N_DRUG; i++) {
        const int deg = __ldg(&nbrD[i]);
        if (deg > 0) {
            const int* row = nbrI + i * MAXDEG;
            float s = 0.f;
            for (int j = half; j < deg; j += 2) {
                int p = __ldg(&row[j]);
                s += fsh[p * 64 + col];
            }
            if (half) red[col] = s;
            __syncthreads();
            if (!half) {
                float tot = s + red[col];
                float fi = fsh[i * 64 + col];
                float avg = tot / (float)deg;
                fsh[i * 64 + col] = (avg + fi) * 0.5f;
            }
            __syncthreads();
        }
    }

    for (int idx = tid; idx < N_DRUG * 64; idx += 128) {
        int r = idx >> 6, c = idx & 63;
        out[(size_t)r * D + cbase + c] = fsh[idx];
    }
}

// ---------------- launch ----------------
extern "C" void kernel_launch(void* const* d_in, const int* in_sizes, int n_in,
                              void* d_out, int out_size) {
    const float* drugW = (const float*)d_in[0];
    const float* relaW = (const float*)d_in[1];
    const float* entW  = (const float*)d_in[2];
    const float* Wa    = (const float*)d_in[3];
    const float* linW  = (const float*)d_in[4];
    const float* linb  = (const float*)d_in[5];
    const float* gamma = (const float*)d_in[6];
    const float* beta  = (const float*)d_in[7];
    const int* names   = (const int*)d_in[8];
    const int* adjT    = (const int*)d_in[9];
    const int* adjR    = (const int*)d_in[10];
    const int* nbrI    = (const int*)d_in[11];
    const int* nbrD    = (const int*)d_in[12];
    const int* epoch   = (const int*)d_in[13];
    float* out = (float*)d_out;

    cudaFuncSetAttribute(k_scan, cudaFuncAttributeMaxDynamicSharedMemorySize,
                         N_DRUG * 64 * (int)sizeof(float));

    k_qgemm<<<dim3(72, 2), 256>>>(drugW, Wa, names);
    k_attn<<<N_DRUG, 256>>>(relaW, entW, adjR, adjT);
    k_lin<<<dim3(72, 2), 256>>>(drugW, linW, linb, names);
    k_bnpart<<<16, D>>>();
    k_bnfin<<<1, D>>>();
    k_norm<<<N_DRUG, D>>>(gamma, beta, out);
    k_scan<<<8, 128, N_DRUG * 64 * sizeof(float)>>>(out, nbrI, nbrD, epoch);
}

// round 3
// speedup vs baseline: 1.5686x; 1.5686x over previous
#include <cuda_runtime.h>
#include <math.h>

#define N_DRUG 572
#define D 512
#define KNBR 64
#define RREL 200
#define MAXDEG 32
#define EPS 1e-5f
#define NBN 64   // bn partial blocks

// ---------------- scratch (no allocs allowed) ----------------
__device__ float g_q[N_DRUG * D];
__device__ float g_agg[N_DRUG * D];
__device__ float g_h[N_DRUG * D];
__device__ float g_psum[NBN * D];
__device__ float g_psumsq[NBN * D];
__device__ float g_mean[D];
__device__ float g_rstd[D];

// ---------------- k1: q = drug_e @ Wa  (8 rows x 256 cols per block) ----------------
__global__ void k_qgemm(const float* __restrict__ drugW,
                        const float* __restrict__ Wa,
                        const int* __restrict__ names) {
    const int r0 = blockIdx.x * 8;
    const int d  = blockIdx.y * 256 + threadIdx.x;
    __shared__ __align__(16) float sh[8][D];
    const int nrows = min(8, N_DRUG - r0);
    for (int idx = threadIdx.x; idx < 8 * D; idx += 256) {
        int r = idx >> 9, c = idx & (D - 1);
        float v = 0.f;
        if (r < nrows) v = drugW[(size_t)names[r0 + r] * D + c];
        sh[r][c] = v;
    }
    __syncthreads();
    float acc[8] = {0.f, 0.f, 0.f, 0.f, 0.f, 0.f, 0.f, 0.f};
    #pragma unroll 4
    for (int k = 0; k < D; k += 4) {
        float w0 = Wa[(k + 0) * D + d];
        float w1 = Wa[(k + 1) * D + d];
        float w2 = Wa[(k + 2) * D + d];
        float w3 = Wa[(k + 3) * D + d];
        #pragma unroll
        for (int r = 0; r < 8; r++) {
            float4 a = *reinterpret_cast<const float4*>(&sh[r][k]);
            acc[r] += a.x * w0 + a.y * w1 + a.z * w2 + a.w * w3;
        }
    }
    for (int r = 0; r < nrows; r++)
        g_q[(size_t)(r0 + r) * D + d] = acc[r];
}

// ---------------- k2: attention scores + softmax + gather-aggregate ----------------
__global__ void k_attn(const float* __restrict__ relaW,
                       const float* __restrict__ entW,
                       const int* __restrict__ adjR,
                       const int* __restrict__ adjT) {
    const int n = blockIdx.x;
    const int tid = threadIdx.x;           // 256 threads
    __shared__ float qsh[D];
    __shared__ float sc[KNBR];
    __shared__ float attn[KNBR];
    __shared__ int relS[KNBR], tailS[KNBR];

    if (tid < KNBR) {
        relS[tid]  = adjR[n * KNBR + tid];
        tailS[tid] = adjT[n * KNBR + tid];
    }
    qsh[tid]       = g_q[(size_t)n * D + tid];
    qsh[tid + 256] = g_q[(size_t)n * D + tid + 256];
    __syncthreads();

    const int w = tid >> 5, lane = tid & 31;
    // 8 warps, each computes 8 dot products of length 512
    #pragma unroll
    for (int kk = 0; kk < 8; kk++) {
        int k = w * 8 + kk;
        const float* base = relaW + (size_t)relS[k] * D;
        float p = 0.f;
        #pragma unroll
        for (int i = 0; i < 16; i++)
            p += qsh[lane + 32 * i] * base[lane + 32 * i];
        #pragma unroll
        for (int off = 16; off; off >>= 1)
            p += __shfl_xor_sync(0xffffffffu, p, off);
        if (lane == 0) sc[k] = p * 0.044194173824159216f;  // 1/sqrt(512)
    }
    __syncthreads();

    if (w == 0) {
        float v0 = sc[lane], v1 = sc[lane + 32];
        float m = fmaxf(v0, v1);
        #pragma unroll
        for (int off = 16; off; off >>= 1)
            m = fmaxf(m, __shfl_xor_sync(0xffffffffu, m, off));
        float e0 = expf(v0 - m), e1 = expf(v1 - m);
        float s = e0 + e1;
        #pragma unroll
        for (int off = 16; off; off >>= 1)
            s += __shfl_xor_sync(0xffffffffu, s, off);
        float inv = 1.f / s;
        attn[lane] = e0 * inv;
        attn[lane + 32] = e1 * inv;
    }
    __syncthreads();

    float a0 = 0.f, a1 = 0.f;
    const int d = tid;
    #pragma unroll 8
    for (int k = 0; k < KNBR; k++) {
        const float* er = entW + (size_t)tailS[k] * D;
        float a = attn[k];
        a0 += a * er[d];
        a1 += a * er[d + 256];
    }
    g_agg[(size_t)n * D + d]       = a0;
    g_agg[(size_t)n * D + d + 256] = a1;
}

// ---------------- k3: h = relu(concat(agg, drug_e) @ lin_W + b) ----------------
__global__ void k_lin(const float* __restrict__ drugW,
                      const float* __restrict__ linW,
                      const float* __restrict__ linb,
                      const int* __restrict__ names) {
    const int r0 = blockIdx.x * 8;
    const int d  = blockIdx.y * 256 + threadIdx.x;
    __shared__ __align__(16) float sh[8][2 * D];    // 32 KB
    const int nrows = min(8, N_DRUG - r0);
    for (int idx = threadIdx.x; idx < 8 * 2 * D; idx += 256) {
        int r = idx >> 10, c = idx & (2 * D - 1);
        float v = 0.f;
        if (r < nrows) {
            if (c < D) v = g_agg[(size_t)(r0 + r) * D + c];
            else       v = drugW[(size_t)names[r0 + r] * D + (c - D)];
        }
        sh[r][c] = v;
    }
    __syncthreads();
    float acc[8] = {0.f, 0.f, 0.f, 0.f, 0.f, 0.f, 0.f, 0.f};
    #pragma unroll 2
    for (int k = 0; k < 2 * D; k += 4) {
        float w0 = linW[(k + 0) * D + d];
        float w1 = linW[(k + 1) * D + d];
        float w2 = linW[(k + 2) * D + d];
        float w3 = linW[(k + 3) * D + d];
        #pragma unroll
        for (int r = 0; r < 8; r++) {
            float4 a = *reinterpret_cast<const float4*>(&sh[r][k]);
            acc[r] += a.x * w0 + a.y * w1 + a.z * w2 + a.w * w3;
        }
    }
    const float b = linb[d];
    for (int r = 0; r < nrows; r++) {
        float v = acc[r] + b;
        g_h[(size_t)(r0 + r) * D + d] = v > 0.f ? v : 0.f;
    }
}

// ---------------- k4: partial BN stats (64 row-slices) ----------------
__global__ void k_bnpart() {
    const int b = blockIdx.x;       // 64 blocks
    const int d = threadIdx.x;      // 512 threads
    const int r0 = b * 9;
    const int r1 = min(N_DRUG, r0 + 9);
    float s = 0.f, sq = 0.f;
    for (int r = r0; r < r1; r++) {
        float v = g_h[(size_t)r * D + d];
        s += v;
        sq += v * v;
    }
    g_psum[b * D + d] = s;
    g_psumsq[b * D + d] = sq;
}

// ---------------- k5: finalize mean/rstd ----------------
__global__ void k_bnfin() {
    const int d = threadIdx.x;
    float s = 0.f, sq = 0.f;
    #pragma unroll
    for (int b = 0; b < NBN; b++) {
        s  += g_psum[b * D + d];
        sq += g_psumsq[b * D + d];
    }
    const float invN = 1.f / (float)N_DRUG;
    float mean = s * invN;
    float var = sq * invN - mean * mean;
    g_mean[d] = mean;
    g_rstd[d] = rsqrtf(var + EPS);
}

// ---------------- k6: normalize + affine -> d_out ----------------
__global__ void k_norm(const float* __restrict__ gamma,
                       const float* __restrict__ beta,
                       float* __restrict__ out) {
    const int n = blockIdx.x;
    const int d = threadIdx.x;
    float v = g_h[(size_t)n * D + d];
    out[(size_t)n * D + d] = (v - g_mean[d]) * g_rstd[d] * gamma[d] + beta[d];
}

// ---------------- k7: sequential neighbor-mean smoothing (v2) ----------------
// Column-exclusive scan: 8 blocks x 64 columns. During the 572-step serial
// chain, thread t (t<64) exclusively owns column t: every smem read
// fsh[p*64+col] and write fsh[i*64+col] touches only its own column, so the
// entire chain runs with ZERO barriers / shuffles. nbr_idx + deg + 1/deg are
// preloaded into shared memory to keep the chain LDS-only.
// Dynamic smem: 572*64*4 (fsh) + 572*32*4 (nbr) + 572*4 (inv) + 572*4 (deg)
//             = 224224 B  (< 227 KB cap)
#define SCAN_SMEM (N_DRUG*64*4 + N_DRUG*32*4 + N_DRUG*4 + N_DRUG*4)

__global__ void k_scan(float* __restrict__ out,
                       const int* __restrict__ nbrI,
                       const int* __restrict__ nbrD,
                       const int* __restrict__ epoch) {
    if (epoch[0] <= 1) return;
    extern __shared__ __align__(16) char dyn[];
    float* fsh  = (float*)dyn;                                  // [572][64]
    int*   nbrS = (int*)(dyn + N_DRUG * 64 * 4);                // [572][32]
    float* invS = (float*)(dyn + N_DRUG * 64 * 4 + N_DRUG * 32 * 4);  // [572]
    int*   degS = (int*)(dyn + N_DRUG * 64 * 4 + N_DRUG * 32 * 4 + N_DRUG * 4);

    const int tid = threadIdx.x;             // 256 threads (load/store phases)
    const int cbase = blockIdx.x * 64;

    for (int idx = tid; idx < N_DRUG * 64; idx += 256) {
        int r = idx >> 6, c = idx & 63;
        fsh[idx] = out[(size_t)r * D + cbase + c];
    }
    for (int idx = tid; idx < N_DRUG * MAXDEG; idx += 256)
        nbrS[idx] = nbrI[idx];
    for (int i = tid; i < N_DRUG; i += 256) {
        int dg = nbrD[i];
        degS[i] = dg;
        invS[i] = 1.0f / (float)(dg > 0 ? dg : 1);
    }
    __syncthreads();

    if (tid < 64) {
        const int col = tid;
        for (int i = 0; i < N_DRUG; i++) {
            const int deg = degS[i];             // uniform per warp
            if (deg == 0) continue;
            const int* nb = &nbrS[i * MAXDEG];
            float a0 = 0.f, a1 = 0.f, a2 = 0.f, a3 = 0.f;
            int j = 0;
            const int d4 = deg & ~3;
            for (; j < d4; j += 4) {
                int p0 = nb[j], p1 = nb[j + 1], p2 = nb[j + 2], p3 = nb[j + 3];
                a0 += fsh[(p0 << 6) + col];
                a1 += fsh[(p1 << 6) + col];
                a2 += fsh[(p2 << 6) + col];
                a3 += fsh[(p3 << 6) + col];
            }
            for (; j < deg; j++)
                a0 += fsh[(nb[j] << 6) + col];
            float s = (a0 + a1) + (a2 + a3);
            // (s/deg + f[i]) * 0.5
            fsh[(i << 6) + col] = fmaf(s, invS[i], fsh[(i << 6) + col]) * 0.5f;
        }
    }
    __syncthreads();

    for (int idx = tid; idx < N_DRUG * 64; idx += 256) {
        int r = idx >> 6, c = idx & 63;
        out[(size_t)r * D + cbase + c] = fsh[idx];
    }
}

// ---------------- launch ----------------
extern "C" void kernel_launch(void* const* d_in, const int* in_sizes, int n_in,
                              void* d_out, int out_size) {
    const float* drugW = (const float*)d_in[0];
    const float* relaW = (const float*)d_in[1];
    const float* entW  = (const float*)d_in[2];
    const float* Wa    = (const float*)d_in[3];
    const float* linW  = (const float*)d_in[4];
    const float* linb  = (const float*)d_in[5];
    const float* gamma = (const float*)d_in[6];
    const float* beta  = (const float*)d_in[7];
    const int* names   = (const int*)d_in[8];
    const int* adjT    = (const int*)d_in[9];
    const int* adjR    = (const int*)d_in[10];
    const int* nbrI    = (const int*)d_in[11];
    const int* nbrD    = (const int*)d_in[12];
    const int* epoch   = (const int*)d_in[13];
    float* out = (float*)d_out;

    static int attr_set = 0;
    if (!attr_set) {
        cudaFuncSetAttribute(k_scan, cudaFuncAttributeMaxDynamicSharedMemorySize,
                             SCAN_SMEM);
        attr_set = 1;
    }

    k_qgemm<<<dim3(72, 2), 256>>>(drugW, Wa, names);
    k_attn<<<N_DRUG, 256>>>(relaW, entW, adjR, adjT);
    k_lin<<<dim3(72, 2), 256>>>(drugW, linW, linb, names);
    k_bnpart<<<NBN, D>>>();
    k_bnfin<<<1, D>>>();
    k_norm<<<N_DRUG, D>>>(gamma, beta, out);
    k_scan<<<8, 256, SCAN_SMEM>>>(out, nbrI, nbrD, epoch);
}

// round 4
// speedup vs baseline: 2.1481x; 1.3694x over previous
#include <cuda_runtime.h>
#include <math.h>

#define N_DRUG 572
#define D 512
#define KNBR 64
#define RREL 200
#define MAXDEG 32
#define EPS 1e-5f
#define NBN 64   // bn partial blocks

// ---------------- scratch (no allocs allowed) ----------------
__device__ float g_q[N_DRUG * D];
__device__ float g_agg[N_DRUG * D];
__device__ float g_h[N_DRUG * D];
__device__ float g_psum[NBN * D];
__device__ float g_psumsq[NBN * D];
__device__ float g_mean[D];
__device__ float g_rstd[D];

// ---------------- k1: q = drug_e @ Wa  (8 rows x 256 cols per block) ----------------
__global__ void k_qgemm(const float* __restrict__ drugW,
                        const float* __restrict__ Wa,
                        const int* __restrict__ names) {
    const int r0 = blockIdx.x * 8;
    const int d  = blockIdx.y * 256 + threadIdx.x;
    __shared__ __align__(16) float sh[8][D];
    const int nrows = min(8, N_DRUG - r0);
    for (int idx = threadIdx.x; idx < 8 * D; idx += 256) {
        int r = idx >> 9, c = idx & (D - 1);
        float v = 0.f;
        if (r < nrows) v = drugW[(size_t)names[r0 + r] * D + c];
        sh[r][c] = v;
    }
    __syncthreads();
    float acc[8] = {0.f, 0.f, 0.f, 0.f, 0.f, 0.f, 0.f, 0.f};
    #pragma unroll 4
    for (int k = 0; k < D; k += 4) {
        float w0 = Wa[(k + 0) * D + d];
        float w1 = Wa[(k + 1) * D + d];
        float w2 = Wa[(k + 2) * D + d];
        float w3 = Wa[(k + 3) * D + d];
        #pragma unroll
        for (int r = 0; r < 8; r++) {
            float4 a = *reinterpret_cast<const float4*>(&sh[r][k]);
            acc[r] += a.x * w0 + a.y * w1 + a.z * w2 + a.w * w3;
        }
    }
    for (int r = 0; r < nrows; r++)
        g_q[(size_t)(r0 + r) * D + d] = acc[r];
}

// ---------------- k2: attention scores + softmax + gather-aggregate ----------------
__global__ void k_attn(const float* __restrict__ relaW,
                       const float* __restrict__ entW,
                       const int* __restrict__ adjR,
                       const int* __restrict__ adjT) {
    const int n = blockIdx.x;
    const int tid = threadIdx.x;           // 256 threads
    __shared__ float qsh[D];
    __shared__ float sc[KNBR];
    __shared__ float attn[KNBR];
    __shared__ int relS[KNBR], tailS[KNBR];

    if (tid < KNBR) {
        relS[tid]  = adjR[n * KNBR + tid];
        tailS[tid] = adjT[n * KNBR + tid];
    }
    qsh[tid]       = g_q[(size_t)n * D + tid];
    qsh[tid + 256] = g_q[(size_t)n * D + tid + 256];
    __syncthreads();

    const int w = tid >> 5, lane = tid & 31;
    // 8 warps, each computes 8 dot products of length 512
    #pragma unroll
    for (int kk = 0; kk < 8; kk++) {
        int k = w * 8 + kk;
        const float* base = relaW + (size_t)relS[k] * D;
        float p = 0.f;
        #pragma unroll
        for (int i = 0; i < 16; i++)
            p += qsh[lane + 32 * i] * base[lane + 32 * i];
        #pragma unroll
        for (int off = 16; off; off >>= 1)
            p += __shfl_xor_sync(0xffffffffu, p, off);
        if (lane == 0) sc[k] = p * 0.044194173824159216f;  // 1/sqrt(512)
    }
    __syncthreads();

    if (w == 0) {
        float v0 = sc[lane], v1 = sc[lane + 32];
        float m = fmaxf(v0, v1);
        #pragma unroll
        for (int off = 16; off; off >>= 1)
            m = fmaxf(m, __shfl_xor_sync(0xffffffffu, m, off));
        float e0 = expf(v0 - m), e1 = expf(v1 - m);
        float s = e0 + e1;
        #pragma unroll
        for (int off = 16; off; off >>= 1)
            s += __shfl_xor_sync(0xffffffffu, s, off);
        float inv = 1.f / s;
        attn[lane] = e0 * inv;
        attn[lane + 32] = e1 * inv;
    }
    __syncthreads();

    float a0 = 0.f, a1 = 0.f;
    const int d = tid;
    #pragma unroll 8
    for (int k = 0; k < KNBR; k++) {
        const float* er = entW + (size_t)tailS[k] * D;
        float a = attn[k];
        a0 += a * er[d];
        a1 += a * er[d + 256];
    }
    g_agg[(size_t)n * D + d]       = a0;
    g_agg[(size_t)n * D + d + 256] = a1;
}

// ---------------- k3: h = relu(concat(agg, drug_e) @ lin_W + b) ----------------
__global__ void k_lin(const float* __restrict__ drugW,
                      const float* __restrict__ linW,
                      const float* __restrict__ linb,
                      const int* __restrict__ names) {
    const int r0 = blockIdx.x * 8;
    const int d  = blockIdx.y * 256 + threadIdx.x;
    __shared__ __align__(16) float sh[8][2 * D];    // 32 KB
    const int nrows = min(8, N_DRUG - r0);
    for (int idx = threadIdx.x; idx < 8 * 2 * D; idx += 256) {
        int r = idx >> 10, c = idx & (2 * D - 1);
        float v = 0.f;
        if (r < nrows) {
            if (c < D) v = g_agg[(size_t)(r0 + r) * D + c];
            else       v = drugW[(size_t)names[r0 + r] * D + (c - D)];
        }
        sh[r][c] = v;
    }
    __syncthreads();
    float acc[8] = {0.f, 0.f, 0.f, 0.f, 0.f, 0.f, 0.f, 0.f};
    #pragma unroll 2
    for (int k = 0; k < 2 * D; k += 4) {
        float w0 = linW[(k + 0) * D + d];
        float w1 = linW[(k + 1) * D + d];
        float w2 = linW[(k + 2) * D + d];
        float w3 = linW[(k + 3) * D + d];
        #pragma unroll
        for (int r = 0; r < 8; r++) {
            float4 a = *reinterpret_cast<const float4*>(&sh[r][k]);
            acc[r] += a.x * w0 + a.y * w1 + a.z * w2 + a.w * w3;
        }
    }
    const float b = linb[d];
    for (int r = 0; r < nrows; r++) {
        float v = acc[r] + b;
        g_h[(size_t)(r0 + r) * D + d] = v > 0.f ? v : 0.f;
    }
}

// ---------------- k4: partial BN stats (64 row-slices) ----------------
__global__ void k_bnpart() {
    const int b = blockIdx.x;       // 64 blocks
    const int d = threadIdx.x;      // 512 threads
    const int r0 = b * 9;
    const int r1 = min(N_DRUG, r0 + 9);
    float s = 0.f, sq = 0.f;
    for (int r = r0; r < r1; r++) {
        float v = g_h[(size_t)r * D + d];
        s += v;
        sq += v * v;
    }
    g_psum[b * D + d] = s;
    g_psumsq[b * D + d] = sq;
}

// ---------------- k5: finalize mean/rstd ----------------
__global__ void k_bnfin() {
    const int d = threadIdx.x;
    float s = 0.f, sq = 0.f;
    #pragma unroll
    for (int b = 0; b < NBN; b++) {
        s  += g_psum[b * D + d];
        sq += g_psumsq[b * D + d];
    }
    const float invN = 1.f / (float)N_DRUG;
    float mean = s * invN;
    float var = sq * invN - mean * mean;
    g_mean[d] = mean;
    g_rstd[d] = rsqrtf(var + EPS);
}

// ---------------- k6: normalize + affine -> d_out ----------------
__global__ void k_norm(const float* __restrict__ gamma,
                       const float* __restrict__ beta,
                       float* __restrict__ out) {
    const int n = blockIdx.x;
    const int d = threadIdx.x;
    float v = g_h[(size_t)n * D + d];
    out[(size_t)n * D + d] = (v - g_mean[d]) * g_rstd[d] * gamma[d] + beta[d];
}

// ---------------- k7: sequential neighbor-mean smoothing (v3) ----------------
// Column-exclusive scan, branch-free + fixed-trip-count inner loop:
//  - fsh has a 573rd all-zero dummy row; nbrS entries for j>=deg point at it,
//    so every step sums exactly 32 neighbors, fully unrolled, no masks.
//  - nbrS holds pre-scaled row offsets (p<<6): address = offset + col, 1 IADD.
//  - indices fetched as int4 (8 x LDS.128 per step instead of 32 x LDS).
//  - deg==0 handled by per-node scales: f_new = s*sc1 + f*sc0 with
//    sc0 = deg>0 ? 0.5 : 1.0, sc1 = deg>0 ? 0.5/deg : 0.0  (s==0 when deg==0).
// Zero barriers / shuffles in the whole 572-step chain.
// smem: 573*64*4 (fsh) + 572*32*4 (nbrS) + 2*572*4 (scales) = 224480 B
#define SCAN_SMEM ((573 * 64 + N_DRUG * MAXDEG + 2 * N_DRUG) * 4)

__global__ void k_scan(float* __restrict__ out,
                       const int* __restrict__ nbrI,
                       const int* __restrict__ nbrD,
                       const int* __restrict__ epoch) {
    if (epoch[0] <= 1) return;
    extern __shared__ __align__(16) char dyn[];
    float* fsh  = (float*)dyn;                                   // [573][64]
    int*   nbrS = (int*)(dyn + 573 * 64 * 4);                    // [572][32]
    float* sc0  = (float*)(dyn + 573 * 64 * 4 + N_DRUG * MAXDEG * 4);  // [572]
    float* sc1  = sc0 + N_DRUG;                                  // [572]

    const int tid = threadIdx.x;             // 256 threads (load/store phases)
    const int cbase = blockIdx.x * 64;

    for (int idx = tid; idx < N_DRUG * 64; idx += 256) {
        int r = idx >> 6, c = idx & 63;
        fsh[idx] = out[(size_t)r * D + cbase + c];
    }
    if (tid < 64) fsh[N_DRUG * 64 + tid] = 0.f;        // dummy zero row
    for (int idx = tid; idx < N_DRUG * MAXDEG; idx += 256) {
        int r = idx >> 5, j = idx & (MAXDEG - 1);
        int dg = __ldg(&nbrD[r]);
        nbrS[idx] = (j < dg ? __ldg(&nbrI[idx]) : N_DRUG) << 6;
    }
    for (int i = tid; i < N_DRUG; i += 256) {
        int dg = nbrD[i];
        sc0[i] = dg > 0 ? 0.5f : 1.0f;
        sc1[i] = dg > 0 ? 0.5f / (float)dg : 0.0f;
    }
    __syncthreads();

    if (tid < 64) {
        const int col = tid;
        const int4* nb4 = (const int4*)nbrS;
        for (int i = 0; i < N_DRUG; i++) {
            float s0 = 0.f, s1 = 0.f, s2 = 0.f, s3 = 0.f;
            #pragma unroll
            for (int q = 0; q < 8; q++) {
                int4 c = nb4[i * 8 + q];
                s0 += fsh[c.x + col];
                s1 += fsh[c.y + col];
                s2 += fsh[c.z + col];
                s3 += fsh[c.w + col];
            }
            float s = (s0 + s1) + (s2 + s3);
            const int fi = (i << 6) + col;
            fsh[fi] = s * sc1[i] + fsh[fi] * sc0[i];
        }
    }
    __syncthreads();

    for (int idx = tid; idx < N_DRUG * 64; idx += 256) {
        int r = idx >> 6, c = idx & 63;
        out[(size_t)r * D + cbase + c] = fsh[idx];
    }
}

// ---------------- launch ----------------
extern "C" void kernel_launch(void* const* d_in, const int* in_sizes, int n_in,
                              void* d_out, int out_size) {
    const float* drugW = (const float*)d_in[0];
    const float* relaW = (const float*)d_in[1];
    const float* entW  = (const float*)d_in[2];
    const float* Wa    = (const float*)d_in[3];
    const float* linW  = (const float*)d_in[4];
    const float* linb  = (const float*)d_in[5];
    const float* gamma = (const float*)d_in[6];
    const float* beta  = (const float*)d_in[7];
    const int* names   = (const int*)d_in[8];
    const int* adjT    = (const int*)d_in[9];
    const int* adjR    = (const int*)d_in[10];
    const int* nbrI    = (const int*)d_in[11];
    const int* nbrD    = (const int*)d_in[12];
    const int* epoch   = (const int*)d_in[13];
    float* out = (float*)d_out;

    static int attr_set = 0;
    if (!attr_set) {
        cudaFuncSetAttribute(k_scan, cudaFuncAttributeMaxDynamicSharedMemorySize,
                             SCAN_SMEM);
        attr_set = 1;
    }

    k_qgemm<<<dim3(72, 2), 256>>>(drugW, Wa, names);
    k_attn<<<N_DRUG, 256>>>(relaW, entW, adjR, adjT);
    k_lin<<<dim3(72, 2), 256>>>(drugW, linW, linb, names);
    k_bnpart<<<NBN, D>>>();
    k_bnfin<<<1, D>>>();
    k_norm<<<N_DRUG, D>>>(gamma, beta, out);
    k_scan<<<8, 256, SCAN_SMEM>>>(out, nbrI, nbrD, epoch);
}

// round 5
// speedup vs baseline: 2.5930x; 1.2071x over previous
#include <cuda_runtime.h>
#include <math.h>

#define N_DRUG 572
#define D 512
#define KNBR 64
#define RREL 200
#define MAXDEG 32
#define EPS 1e-5f
#define NBN 64   // bn partial blocks

// ---------------- scratch (no allocs allowed) ----------------
__device__ float g_q[N_DRUG * D];
__device__ float g_agg[N_DRUG * D];
__device__ float g_h[N_DRUG * D];
__device__ float g_psum[NBN * D];
__device__ float g_psumsq[NBN * D];
__device__ float g_mean[D];
__device__ float g_rstd[D];
// wave schedule (computed by k_wave each call, deterministic)
__device__ int g_order[N_DRUG];
__device__ int g_wstart[N_DRUG + 2];
__device__ int g_nwaves;

// ---------------- k1: q = drug_e @ Wa ----------------
__global__ void k_qgemm(const float* __restrict__ drugW,
                        const float* __restrict__ Wa,
                        const int* __restrict__ names) {
    const int r0 = blockIdx.x * 8;
    const int d  = blockIdx.y * 256 + threadIdx.x;
    __shared__ __align__(16) float sh[8][D];
    const int nrows = min(8, N_DRUG - r0);
    for (int idx = threadIdx.x; idx < 8 * D; idx += 256) {
        int r = idx >> 9, c = idx & (D - 1);
        float v = 0.f;
        if (r < nrows) v = drugW[(size_t)names[r0 + r] * D + c];
        sh[r][c] = v;
    }
    __syncthreads();
    float acc[8] = {0.f, 0.f, 0.f, 0.f, 0.f, 0.f, 0.f, 0.f};
    #pragma unroll 4
    for (int k = 0; k < D; k += 4) {
        float w0 = Wa[(k + 0) * D + d];
        float w1 = Wa[(k + 1) * D + d];
        float w2 = Wa[(k + 2) * D + d];
        float w3 = Wa[(k + 3) * D + d];
        #pragma unroll
        for (int r = 0; r < 8; r++) {
            float4 a = *reinterpret_cast<const float4*>(&sh[r][k]);
            acc[r] += a.x * w0 + a.y * w1 + a.z * w2 + a.w * w3;
        }
    }
    for (int r = 0; r < nrows; r++)
        g_q[(size_t)(r0 + r) * D + d] = acc[r];
}

// ---------------- k2: attention + softmax + gather-aggregate ----------------
__global__ void k_attn(const float* __restrict__ relaW,
                       const float* __restrict__ entW,
                       const int* __restrict__ adjR,
                       const int* __restrict__ adjT) {
    const int n = blockIdx.x;
    const int tid = threadIdx.x;           // 256 threads
    __shared__ float qsh[D];
    __shared__ float sc[KNBR];
    __shared__ float attn[KNBR];
    __shared__ int relS[KNBR], tailS[KNBR];

    if (tid < KNBR) {
        relS[tid]  = adjR[n * KNBR + tid];
        tailS[tid] = adjT[n * KNBR + tid];
    }
    qsh[tid]       = g_q[(size_t)n * D + tid];
    qsh[tid + 256] = g_q[(size_t)n * D + tid + 256];
    __syncthreads();

    const int w = tid >> 5, lane = tid & 31;
    #pragma unroll
    for (int kk = 0; kk < 8; kk++) {
        int k = w * 8 + kk;
        const float* base = relaW + (size_t)relS[k] * D;
        float p = 0.f;
        #pragma unroll
        for (int i = 0; i < 16; i++)
            p += qsh[lane + 32 * i] * base[lane + 32 * i];
        #pragma unroll
        for (int off = 16; off; off >>= 1)
            p += __shfl_xor_sync(0xffffffffu, p, off);
        if (lane == 0) sc[k] = p * 0.044194173824159216f;  // 1/sqrt(512)
    }
    __syncthreads();

    if (w == 0) {
        float v0 = sc[lane], v1 = sc[lane + 32];
        float m = fmaxf(v0, v1);
        #pragma unroll
        for (int off = 16; off; off >>= 1)
            m = fmaxf(m, __shfl_xor_sync(0xffffffffu, m, off));
        float e0 = expf(v0 - m), e1 = expf(v1 - m);
        float s = e0 + e1;
        #pragma unroll
        for (int off = 16; off; off >>= 1)
            s += __shfl_xor_sync(0xffffffffu, s, off);
        float inv = 1.f / s;
        attn[lane] = e0 * inv;
        attn[lane + 32] = e1 * inv;
    }
    __syncthreads();

    float a0 = 0.f, a1 = 0.f;
    const int d = tid;
    #pragma unroll 8
    for (int k = 0; k < KNBR; k++) {
        const float* er = entW + (size_t)tailS[k] * D;
        float a = attn[k];
        a0 += a * er[d];
        a1 += a * er[d + 256];
    }
    g_agg[(size_t)n * D + d]       = a0;
    g_agg[(size_t)n * D + d + 256] = a1;
}

// ---------------- k3: h = relu(concat(agg, drug_e) @ lin_W + b) ----------------
__global__ void k_lin(const float* __restrict__ drugW,
                      const float* __restrict__ linW,
                      const float* __restrict__ linb,
                      const int* __restrict__ names) {
    const int r0 = blockIdx.x * 8;
    const int d  = blockIdx.y * 256 + threadIdx.x;
    __shared__ __align__(16) float sh[8][2 * D];    // 32 KB
    const int nrows = min(8, N_DRUG - r0);
    for (int idx = threadIdx.x; idx < 8 * 2 * D; idx += 256) {
        int r = idx >> 10, c = idx & (2 * D - 1);
        float v = 0.f;
        if (r < nrows) {
            if (c < D) v = g_agg[(size_t)(r0 + r) * D + c];
            else       v = drugW[(size_t)names[r0 + r] * D + (c - D)];
        }
        sh[r][c] = v;
    }
    __syncthreads();
    float acc[8] = {0.f, 0.f, 0.f, 0.f, 0.f, 0.f, 0.f, 0.f};
    #pragma unroll 2
    for (int k = 0; k < 2 * D; k += 4) {
        float w0 = linW[(k + 0) * D + d];
        float w1 = linW[(k + 1) * D + d];
        float w2 = linW[(k + 2) * D + d];
        float w3 = linW[(k + 3) * D + d];
        #pragma unroll
        for (int r = 0; r < 8; r++) {
            float4 a = *reinterpret_cast<const float4*>(&sh[r][k]);
            acc[r] += a.x * w0 + a.y * w1 + a.z * w2 + a.w * w3;
        }
    }
    const float b = linb[d];
    for (int r = 0; r < nrows; r++) {
        float v = acc[r] + b;
        g_h[(size_t)(r0 + r) * D + d] = v > 0.f ? v : 0.f;
    }
}

// ---------------- k4/k5/k6: BatchNorm ----------------
__global__ void k_bnpart() {
    const int b = blockIdx.x;       // 64 blocks
    const int d = threadIdx.x;      // 512 threads
    const int r0 = b * 9;
    const int r1 = min(N_DRUG, r0 + 9);
    float s = 0.f, sq = 0.f;
    for (int r = r0; r < r1; r++) {
        float v = g_h[(size_t)r * D + d];
        s += v;
        sq += v * v;
    }
    g_psum[b * D + d] = s;
    g_psumsq[b * D + d] = sq;
}

__global__ void k_bnfin() {
    const int d = threadIdx.x;
    float s = 0.f, sq = 0.f;
    #pragma unroll
    for (int b = 0; b < NBN; b++) {
        s  += g_psum[b * D + d];
        sq += g_psumsq[b * D + d];
    }
    const float invN = 1.f / (float)N_DRUG;
    float mean = s * invN;
    float var = sq * invN - mean * mean;
    g_mean[d] = mean;
    g_rstd[d] = rsqrtf(var + EPS);
}

__global__ void k_norm(const float* __restrict__ gamma,
                       const float* __restrict__ beta,
                       float* __restrict__ out) {
    const int n = blockIdx.x;
    const int d = threadIdx.x;
    float v = g_h[(size_t)n * D + d];
    out[(size_t)n * D + d] = (v - g_mean[d]) * g_rstd[d] * gamma[d] + beta[d];
}

// ---------------- k_wave: topological wave schedule (Kahn BFS) --------------
// True dependency of sequential step i: all j<i with j in nbr[i] (read updated
// value). Anti-deps (p>i read pre-update) removed in k_scan via old/new double
// buffer, so only the p<i DAG constrains order. This kernel computes
// order[] grouped into waves + wave boundaries, all in one block's smem.
#define WAVE_SMEM ((N_DRUG * 4 /*indeg,scnt,cur,order*/ \
                   + (N_DRUG + 1) /*soff*/ + (N_DRUG + 2) /*wstart*/ \
                   + N_DRUG * MAXDEG /*succ*/ + 4 /*counters*/) * 4)

__global__ void k_wave(const int* __restrict__ nbrI,
                       const int* __restrict__ nbrD,
                       const int* __restrict__ epoch) {
    if (epoch[0] <= 1) return;
    extern __shared__ int ws[];
    int* indeg  = ws;                          // [572]
    int* scnt   = indeg + N_DRUG;              // [572]
    int* cur    = scnt + N_DRUG;               // [572]
    int* order  = cur + N_DRUG;                // [572]
    int* soff   = order + N_DRUG;              // [573]
    int* wstart = soff + N_DRUG + 1;           // [574]
    int* succ   = wstart + N_DRUG + 2;         // [572*32]
    int* counters = succ + N_DRUG * MAXDEG;    // [4]

    const int tid = threadIdx.x;               // 512
    const int wid = tid >> 5, lane = tid & 31;

    for (int i = tid; i < N_DRUG; i += 512) { indeg[i] = 0; scnt[i] = 0; }
    if (tid == 0) counters[0] = 0;
    __syncthreads();

    // pred counts + succ counts (multiplicity preserved)
    for (int i = tid; i < N_DRUG; i += 512) {
        int dg = nbrD[i];
        int cnt = 0;
        for (int j = 0; j < dg; j++) {
            int p = nbrI[i * MAXDEG + j];
            if (p < i) { cnt++; atomicAdd(&scnt[p], 1); }
        }
        indeg[i] = cnt;
    }
    __syncthreads();

    // exclusive scan of scnt -> soff (warp 0, chunked)
    if (wid == 0) {
        const int CH = 18;                     // 32*18 = 576 >= 572
        int lo = lane * CH, hi = min(N_DRUG, lo + CH);
        int s = 0;
        for (int k = lo; k < hi; k++) s += scnt[k];
        // exclusive warp scan
        int v = s;
        #pragma unroll
        for (int off = 1; off < 32; off <<= 1) {
            int t = __shfl_up_sync(0xffffffffu, v, off);
            if (lane >= off) v += t;
        }
        int excl = v - s;
        int run = excl;
        for (int k = lo; k < hi; k++) {
            soff[k] = run; cur[k] = run; run += scnt[k];
        }
        if (lane == 31) soff[N_DRUG] = run;
    }
    __syncthreads();

    // fill successor lists
    for (int i = tid; i < N_DRUG; i += 512) {
        int dg = nbrD[i];
        for (int j = 0; j < dg; j++) {
            int p = nbrI[i * MAXDEG + j];
            if (p < i) {
                int pos = atomicAdd(&cur[p], 1);
                succ[pos] = i;
            }
        }
    }
    __syncthreads();

    // wave 0: indeg == 0
    for (int i = tid; i < N_DRUG; i += 512)
        if (indeg[i] == 0) {
            int pos = atomicAdd(&counters[0], 1);
            order[pos] = i;
        }
    __syncthreads();

    int wbase = 0;
    int placed = counters[0];
    int wcount = placed;
    int w = 0;
    if (tid == 0) { wstart[0] = 0; wstart[1] = placed; }
    __syncthreads();

    while (placed < N_DRUG && wcount > 0) {
        // warp-per-frontier-node, lane-per-edge
        for (int slot = wbase + wid; slot < wbase + wcount; slot += 16) {
            int n = order[slot];
            int s0 = soff[n], s1 = soff[n + 1];
            for (int e = s0 + lane; e < s1; e += 32) {
                int sn = succ[e];
                if (atomicSub(&indeg[sn], 1) == 1) {
                    int pos = atomicAdd(&counters[0], 1);
                    order[pos] = sn;
                }
            }
        }
        __syncthreads();
        wbase += wcount;
        int total = counters[0];
        wcount = total - placed;
        placed = total;
        w++;
        if (tid == 0) wstart[w + 1] = total;
        __syncthreads();
    }

    const int nwaves = w + 1;
    for (int i = tid; i < N_DRUG; i += 512) g_order[i] = order[i];
    for (int i = tid; i <= nwaves; i += 512) g_wstart[i] = wstart[i];
    if (tid == 0) g_nwaves = nwaves;
}

// ---------------- k7: wave-parallel neighbor-mean smoothing (v4) ------------
// Two-buffer: old (pre-scan values, immutable, + zero dummy row) and new
// (written once per node). value(p) for node i = new[p] if p<i else old[p];
// the selection is baked into precomputed smem offsets, so the wave loop is
// branch-free: 8 bcast int4 offset loads + 32 data LDS + tree per node.
// 16 blocks x 32 columns; 8 warps -> 8 nodes concurrently per wave.
// smem: old 573*32 + new 572*32 + idx 572*32 + sc 2*572 + order 572 + wstart 574
#define SC_NEWOFF (573 * 32)                 // float offset of new region
#define SC_DUMMY  (N_DRUG * 32)              // zero row in old region
#define SCAN_SMEM ((573 * 32 + N_DRUG * 32 + N_DRUG * 32 + 2 * N_DRUG \
                    + N_DRUG + (N_DRUG + 2)) * 4)

__global__ void k_scan(float* __restrict__ out,
                       const int* __restrict__ nbrI,
                       const int* __restrict__ nbrD,
                       const int* __restrict__ epoch) {
    if (epoch[0] <= 1) return;
    extern __shared__ __align__(16) char dyn[];
    float* fsh  = (float*)dyn;                         // old[573*32] ++ new[572*32]
    int*   idxS = (int*)(dyn + (573 * 32 + N_DRUG * 32) * 4);
    float* sc0  = (float*)((char*)idxS + N_DRUG * 32 * 4);
    float* sc1  = sc0 + N_DRUG;
    int*   orderS  = (int*)(sc1 + N_DRUG);
    int*   wstartS = orderS + N_DRUG;

    const int tid = threadIdx.x;               // 256
    const int cbase = blockIdx.x * 32;

    for (int idx = tid; idx < N_DRUG * 32; idx += 256) {
        int r = idx >> 5, c = idx & 31;
        fsh[idx] = out[(size_t)r * D + cbase + c];
    }
    if (tid < 32) fsh[SC_DUMMY + tid] = 0.f;

    for (int idx = tid; idx < N_DRUG * 32; idx += 256) {
        int r = idx >> 5, j = idx & 31;
        int dg = __ldg(&nbrD[r]);
        int p  = __ldg(&nbrI[idx]);
        int off;
        if (j < dg) off = (p << 5) + (p < r ? SC_NEWOFF : 0);
        else        off = SC_DUMMY;
        idxS[idx] = off;
    }
    for (int i = tid; i < N_DRUG; i += 256) {
        int dg = nbrD[i];
        sc0[i] = dg > 0 ? 0.5f : 1.0f;
        sc1[i] = dg > 0 ? 0.5f / (float)dg : 0.0f;
        orderS[i] = g_order[i];
    }
    const int nw = g_nwaves;
    for (int i = tid; i <= nw; i += 256) wstartS[i] = g_wstart[i];
    __syncthreads();

    const int wid = tid >> 5, lane = tid & 31;
    for (int w = 0; w < nw; w++) {
        const int s = wstartS[w], e = wstartS[w + 1];
        for (int slot = s + wid; slot < e; slot += 8) {
            const int i = orderS[slot];
            const int4* io4 = (const int4*)(idxS + (i << 5));
            float a0 = 0.f, a1 = 0.f, a2 = 0.f, a3 = 0.f;
            #pragma unroll
            for (int q = 0; q < 8; q++) {
                int4 c = io4[q];
                a0 += fsh[c.x + lane];
                a1 += fsh[c.y + lane];
                a2 += fsh[c.z + lane];
                a3 += fsh[c.w + lane];
            }
            float sm = (a0 + a1) + (a2 + a3);
            const int fi = (i << 5) + lane;
            fsh[SC_NEWOFF + fi] = sm * sc1[i] + fsh[fi] * sc0[i];
        }
        __syncthreads();
    }

    for (int idx = tid; idx < N_DRUG * 32; idx += 256) {
        int r = idx >> 5, c = idx & 31;
        out[(size_t)r * D + cbase + c] = fsh[SC_NEWOFF + idx];
    }
}

// ---------------- launch ----------------
extern "C" void kernel_launch(void* const* d_in, const int* in_sizes, int n_in,
                              void* d_out, int out_size) {
    const float* drugW = (const float*)d_in[0];
    const float* relaW = (const float*)d_in[1];
    const float* entW  = (const float*)d_in[2];
    const float* Wa    = (const float*)d_in[3];
    const float* linW  = (const float*)d_in[4];
    const float* linb  = (const float*)d_in[5];
    const float* gamma = (const float*)d_in[6];
    const float* beta  = (const float*)d_in[7];
    const int* names   = (const int*)d_in[8];
    const int* adjT    = (const int*)d_in[9];
    const int* adjR    = (const int*)d_in[10];
    const int* nbrI    = (const int*)d_in[11];
    const int* nbrD    = (const int*)d_in[12];
    const int* epoch   = (const int*)d_in[13];
    float* out = (float*)d_out;

    cudaFuncSetAttribute(k_scan, cudaFuncAttributeMaxDynamicSharedMemorySize,
                         SCAN_SMEM);
    cudaFuncSetAttribute(k_wave, cudaFuncAttributeMaxDynamicSharedMemorySize,
                         WAVE_SMEM);

    k_wave<<<1, 512, WAVE_SMEM>>>(nbrI, nbrD, epoch);
    k_qgemm<<<dim3(72, 2), 256>>>(drugW, Wa, names);
    k_attn<<<N_DRUG, 256>>>(relaW, entW, adjR, adjT);
    k_lin<<<dim3(72, 2), 256>>>(drugW, linW, linb, names);
    k_bnpart<<<NBN, D>>>();
    k_bnfin<<<1, D>>>();
    k_norm<<<N_DRUG, D>>>(gamma, beta, out);
    k_scan<<<16, 256, SCAN_SMEM>>>(out, nbrI, nbrD, epoch);
}

// round 6
// speedup vs baseline: 3.2747x; 1.2629x over previous
#include <cuda_runtime.h>
#include <math.h>

#define N_DRUG 572
#define D 512
#define KNBR 64
#define RREL 200
#define MAXDEG 32
#define EPS 1e-5f
#define NBN 64   // bn partial blocks

// ---------------- scratch (no allocs allowed) ----------------
__device__ float g_q[N_DRUG * D];
__device__ float g_agg[N_DRUG * D];
__device__ float g_h[N_DRUG * D];
__device__ float g_psum[NBN * D];
__device__ float g_psumsq[NBN * D];
__device__ float g_mean[D];
__device__ float g_rstd[D];
// wave schedule (computed by k_wave each call, deterministic)
__device__ int g_order[N_DRUG];
__device__ int g_wstart[N_DRUG + 2];
__device__ int g_nwaves;

// ============ tiled GEMM kernels: BM=32, BN=64, BK=16, 256 thr, 2x4 tile ====
// grid (18, 8).  As staged transposed [k][m] pad-34 (conflict-free stores,
// broadcast float2 reads); Bs [k][n] pad-68 (float4 reads, conflict-free).
// Double-buffered: chunk c+1 LDG'd into regs before computing chunk c, so
// L2 latency hides behind 128 FFMA/thread/chunk.

// ---------------- k1: q = drug_e @ Wa ----------------
__global__ void k_qgemm(const float* __restrict__ drugW,
                        const float* __restrict__ Wa,
                        const int* __restrict__ names) {
    __shared__ float As[2][16][34];
    __shared__ float Bs[2][16][68];
    __shared__ int nm[32];
    const int tid = threadIdx.x;
    const int m0 = blockIdx.x * 32;
    const int n0 = blockIdx.y * 64;
    if (tid < 32) {
        int r = m0 + tid;
        nm[tid] = r < N_DRUG ? names[r] : 0;
    }
    const int lk = tid & 15;       // A loader: k within chunk
    const int lm = tid >> 4;       // A loader: row (2 passes)
    const int bn = tid & 63;       // B loader: col
    const int bk = tid >> 2 >> 4;  // = tid>>6: B loader k (4 passes)
    const int ty = tid >> 4, tx = tid & 15;
    __syncthreads();

    float acc[2][4] = {{0.f,0.f,0.f,0.f},{0.f,0.f,0.f,0.f}};

    // prologue: chunk 0
    #pragma unroll
    for (int p = 0; p < 2; p++) {
        int m = lm + p * 16;
        float v = (m0 + m < N_DRUG) ? drugW[(size_t)nm[m] * D + lk] : 0.f;
        As[0][lk][m] = v;
    }
    #pragma unroll
    for (int p = 0; p < 4; p++) {
        int kk = bk + p * 4;
        Bs[0][kk][bn] = Wa[(size_t)kk * D + n0 + bn];
    }
    __syncthreads();

    int buf = 0;
    const int NCH = D / 16;       // 32
    for (int ch = 0; ch < NCH; ch++) {
        float a_ld[2], b_ld[4];
        const bool has = (ch + 1 < NCH);
        if (has) {
            const int k1 = (ch + 1) * 16;
            #pragma unroll
            for (int p = 0; p < 2; p++) {
                int m = lm + p * 16;
                a_ld[p] = (m0 + m < N_DRUG)
                          ? drugW[(size_t)nm[m] * D + k1 + lk] : 0.f;
            }
            #pragma unroll
            for (int p = 0; p < 4; p++) {
                int kk = bk + p * 4;
                b_ld[p] = Wa[(size_t)(k1 + kk) * D + n0 + bn];
            }
        }
        #pragma unroll
        for (int kk = 0; kk < 16; kk++) {
            float2 a = *(const float2*)&As[buf][kk][2 * ty];
            float4 b = *(const float4*)&Bs[buf][kk][4 * tx];
            acc[0][0] += a.x * b.x; acc[0][1] += a.x * b.y;
            acc[0][2] += a.x * b.z; acc[0][3] += a.x * b.w;
            acc[1][0] += a.y * b.x; acc[1][1] += a.y * b.y;
            acc[1][2] += a.y * b.z; acc[1][3] += a.y * b.w;
        }
        if (has) {
            #pragma unroll
            for (int p = 0; p < 2; p++) As[buf ^ 1][lk][lm + p * 16] = a_ld[p];
            #pragma unroll
            for (int p = 0; p < 4; p++) Bs[buf ^ 1][bk + p * 4][bn] = b_ld[p];
        }
        __syncthreads();
        buf ^= 1;
    }

    #pragma unroll
    for (int r = 0; r < 2; r++) {
        int row = m0 + 2 * ty + r;
        if (row < N_DRUG) {
            float4 v = make_float4(acc[r][0], acc[r][1], acc[r][2], acc[r][3]);
            *(float4*)&g_q[(size_t)row * D + n0 + 4 * tx] = v;
        }
    }
}

// ---------------- k3: h = relu(concat(agg, drug_e) @ lin_W + b) -------------
__global__ void k_lin(const float* __restrict__ drugW,
                      const float* __restrict__ linW,
                      const float* __restrict__ linb,
                      const int* __restrict__ names) {
    __shared__ float As[2][16][34];
    __shared__ float Bs[2][16][68];
    __shared__ int nm[32];
    const int tid = threadIdx.x;
    const int m0 = blockIdx.x * 32;
    const int n0 = blockIdx.y * 64;
    if (tid < 32) {
        int r = m0 + tid;
        nm[tid] = r < N_DRUG ? names[r] : 0;
    }
    const int lk = tid & 15;
    const int lm = tid >> 4;
    const int bn = tid & 63;
    const int bk = tid >> 6;
    const int ty = tid >> 4, tx = tid & 15;
    __syncthreads();

    float acc[2][4] = {{0.f,0.f,0.f,0.f},{0.f,0.f,0.f,0.f}};

    // A element: k<D -> g_agg[row][k], else drugW[name][k-D]; pad rows -> 0
    #pragma unroll
    for (int p = 0; p < 2; p++) {
        int m = lm + p * 16;
        int row = m0 + m;
        float v = 0.f;
        if (row < N_DRUG) v = g_agg[(size_t)row * D + lk];   // chunk0: k<D
        As[0][lk][m] = v;
    }
    #pragma unroll
    for (int p = 0; p < 4; p++) {
        int kk = bk + p * 4;
        Bs[0][kk][bn] = linW[(size_t)kk * D + n0 + bn];
    }
    __syncthreads();

    int buf = 0;
    const int NCH = (2 * D) / 16;     // 64
    for (int ch = 0; ch < NCH; ch++) {
        float a_ld[2], b_ld[4];
        const bool has = (ch + 1 < NCH);
        if (has) {
            const int k1 = (ch + 1) * 16;
            #pragma unroll
            for (int p = 0; p < 2; p++) {
                int m = lm + p * 16;
                int row = m0 + m;
                int k = k1 + lk;
                float v = 0.f;
                if (row < N_DRUG)
                    v = (k < D) ? g_agg[(size_t)row * D + k]
                                : drugW[(size_t)nm[m] * D + (k - D)];
                a_ld[p] = v;
            }
            #pragma unroll
            for (int p = 0; p < 4; p++) {
                int kk = bk + p * 4;
                b_ld[p] = linW[(size_t)(k1 + kk) * D + n0 + bn];
            }
        }
        #pragma unroll
        for (int kk = 0; kk < 16; kk++) {
            float2 a = *(const float2*)&As[buf][kk][2 * ty];
            float4 b = *(const float4*)&Bs[buf][kk][4 * tx];
            acc[0][0] += a.x * b.x; acc[0][1] += a.x * b.y;
            acc[0][2] += a.x * b.z; acc[0][3] += a.x * b.w;
            acc[1][0] += a.y * b.x; acc[1][1] += a.y * b.y;
            acc[1][2] += a.y * b.z; acc[1][3] += a.y * b.w;
        }
        if (has) {
            #pragma unroll
            for (int p = 0; p < 2; p++) As[buf ^ 1][lk][lm + p * 16] = a_ld[p];
            #pragma unroll
            for (int p = 0; p < 4; p++) Bs[buf ^ 1][bk + p * 4][bn] = b_ld[p];
        }
        __syncthreads();
        buf ^= 1;
    }

    const int col = n0 + 4 * tx;
    float4 bb = *(const float4*)&linb[col];
    #pragma unroll
    for (int r = 0; r < 2; r++) {
        int row = m0 + 2 * ty + r;
        if (row < N_DRUG) {
            float4 v;
            v.x = fmaxf(acc[r][0] + bb.x, 0.f);
            v.y = fmaxf(acc[r][1] + bb.y, 0.f);
            v.z = fmaxf(acc[r][2] + bb.z, 0.f);
            v.w = fmaxf(acc[r][3] + bb.w, 0.f);
            *(float4*)&g_h[(size_t)row * D + col] = v;
        }
    }
}

// ---------------- k2: attention + softmax + gather-aggregate ----------------
__global__ void k_attn(const float* __restrict__ relaW,
                       const float* __restrict__ entW,
                       const int* __restrict__ adjR,
                       const int* __restrict__ adjT) {
    const int n = blockIdx.x;
    const int tid = threadIdx.x;           // 256 threads
    __shared__ float qsh[D];
    __shared__ float sc[KNBR];
    __shared__ float attn[KNBR];
    __shared__ int relS[KNBR], tailS[KNBR];

    if (tid < KNBR) {
        relS[tid]  = adjR[n * KNBR + tid];
        tailS[tid] = adjT[n * KNBR + tid];
    }
    qsh[tid]       = g_q[(size_t)n * D + tid];
    qsh[tid + 256] = g_q[(size_t)n * D + tid + 256];
    __syncthreads();

    const int w = tid >> 5, lane = tid & 31;
    #pragma unroll
    for (int kk = 0; kk < 8; kk++) {
        int k = w * 8 + kk;
        const float* base = relaW + (size_t)relS[k] * D;
        float p = 0.f;
        #pragma unroll
        for (int i = 0; i < 16; i++)
            p += qsh[lane + 32 * i] * base[lane + 32 * i];
        #pragma unroll
        for (int off = 16; off; off >>= 1)
            p += __shfl_xor_sync(0xffffffffu, p, off);
        if (lane == 0) sc[k] = p * 0.044194173824159216f;  // 1/sqrt(512)
    }
    __syncthreads();

    if (w == 0) {
        float v0 = sc[lane], v1 = sc[lane + 32];
        float m = fmaxf(v0, v1);
        #pragma unroll
        for (int off = 16; off; off >>= 1)
            m = fmaxf(m, __shfl_xor_sync(0xffffffffu, m, off));
        float e0 = expf(v0 - m), e1 = expf(v1 - m);
        float s = e0 + e1;
        #pragma unroll
        for (int off = 16; off; off >>= 1)
            s += __shfl_xor_sync(0xffffffffu, s, off);
        float inv = 1.f / s;
        attn[lane] = e0 * inv;
        attn[lane + 32] = e1 * inv;
    }
    __syncthreads();

    float a0 = 0.f, a1 = 0.f;
    const int d = tid;
    #pragma unroll 8
    for (int k = 0; k < KNBR; k++) {
        const float* er = entW + (size_t)tailS[k] * D;
        float a = attn[k];
        a0 += a * er[d];
        a1 += a * er[d + 256];
    }
    g_agg[(size_t)n * D + d]       = a0;
    g_agg[(size_t)n * D + d + 256] = a1;
}

// ---------------- k4/k5/k6: BatchNorm ----------------
__global__ void k_bnpart() {
    const int b = blockIdx.x;       // 64 blocks
    const int d = threadIdx.x;      // 512 threads
    const int r0 = b * 9;
    const int r1 = min(N_DRUG, r0 + 9);
    float s = 0.f, sq = 0.f;
    for (int r = r0; r < r1; r++) {
        float v = g_h[(size_t)r * D + d];
        s += v;
        sq += v * v;
    }
    g_psum[b * D + d] = s;
    g_psumsq[b * D + d] = sq;
}

__global__ void k_bnfin() {
    const int d = threadIdx.x;
    float s = 0.f, sq = 0.f;
    #pragma unroll
    for (int b = 0; b < NBN; b++) {
        s  += g_psum[b * D + d];
        sq += g_psumsq[b * D + d];
    }
    const float invN = 1.f / (float)N_DRUG;
    float mean = s * invN;
    float var = sq * invN - mean * mean;
    g_mean[d] = mean;
    g_rstd[d] = rsqrtf(var + EPS);
}

__global__ void k_norm(const float* __restrict__ gamma,
                       const float* __restrict__ beta,
                       float* __restrict__ out) {
    const int n = blockIdx.x;
    const int d = threadIdx.x;
    float v = g_h[(size_t)n * D + d];
    out[(size_t)n * D + d] = (v - g_mean[d]) * g_rstd[d] * gamma[d] + beta[d];
}

// ---------------- k_wave: topological wave schedule (Kahn BFS) --------------
#define WAVE_SMEM ((N_DRUG * 4 /*indeg,scnt,cur,order*/ \
                   + (N_DRUG + 1) /*soff*/ + (N_DRUG + 2) /*wstart*/ \
                   + N_DRUG * MAXDEG /*succ*/ + 4 /*counters*/) * 4)

__global__ void k_wave(const int* __restrict__ nbrI,
                       const int* __restrict__ nbrD,
                       const int* __restrict__ epoch) {
    if (epoch[0] <= 1) return;
    extern __shared__ int ws[];
    int* indeg  = ws;                          // [572]
    int* scnt   = indeg + N_DRUG;              // [572]
    int* cur    = scnt + N_DRUG;               // [572]
    int* order  = cur + N_DRUG;                // [572]
    int* soff   = order + N_DRUG;              // [573]
    int* wstart = soff + N_DRUG + 1;           // [574]
    int* succ   = wstart + N_DRUG + 2;         // [572*32]
    int* counters = succ + N_DRUG * MAXDEG;    // [4]

    const int tid = threadIdx.x;               // 512
    const int wid = tid >> 5, lane = tid & 31;

    for (int i = tid; i < N_DRUG; i += 512) { indeg[i] = 0; scnt[i] = 0; }
    if (tid == 0) counters[0] = 0;
    __syncthreads();

    for (int i = tid; i < N_DRUG; i += 512) {
        int dg = nbrD[i];
        int cnt = 0;
        for (int j = 0; j < dg; j++) {
            int p = nbrI[i * MAXDEG + j];
            if (p < i) { cnt++; atomicAdd(&scnt[p], 1); }
        }
        indeg[i] = cnt;
    }
    __syncthreads();

    if (wid == 0) {
        const int CH = 18;
        int lo = lane * CH, hi = min(N_DRUG, lo + CH);
        int s = 0;
        for (int k = lo; k < hi; k++) s += scnt[k];
        int v = s;
        #pragma unroll
        for (int off = 1; off < 32; off <<= 1) {
            int t = __shfl_up_sync(0xffffffffu, v, off);
            if (lane >= off) v += t;
        }
        int excl = v - s;
        int run = excl;
        for (int k = lo; k < hi; k++) {
            soff[k] = run; cur[k] = run; run += scnt[k];
        }
        if (lane == 31) soff[N_DRUG] = run;
    }
    __syncthreads();

    for (int i = tid; i < N_DRUG; i += 512) {
        int dg = nbrD[i];
        for (int j = 0; j < dg; j++) {
            int p = nbrI[i * MAXDEG + j];
            if (p < i) {
                int pos = atomicAdd(&cur[p], 1);
                succ[pos] = i;
            }
        }
    }
    __syncthreads();

    for (int i = tid; i < N_DRUG; i += 512)
        if (indeg[i] == 0) {
            int pos = atomicAdd(&counters[0], 1);
            order[pos] = i;
        }
    __syncthreads();

    int wbase = 0;
    int placed = counters[0];
    int wcount = placed;
    int w = 0;
    if (tid == 0) { wstart[0] = 0; wstart[1] = placed; }
    __syncthreads();

    while (placed < N_DRUG && wcount > 0) {
        for (int slot = wbase + wid; slot < wbase + wcount; slot += 16) {
            int n = order[slot];
            int s0 = soff[n], s1 = soff[n + 1];
            for (int e = s0 + lane; e < s1; e += 32) {
                int sn = succ[e];
                if (atomicSub(&indeg[sn], 1) == 1) {
                    int pos = atomicAdd(&counters[0], 1);
                    order[pos] = sn;
                }
            }
        }
        __syncthreads();
        wbase += wcount;
        int total = counters[0];
        wcount = total - placed;
        placed = total;
        w++;
        if (tid == 0) wstart[w + 1] = total;
        __syncthreads();
    }

    const int nwaves = w + 1;
    for (int i = tid; i < N_DRUG; i += 512) g_order[i] = order[i];
    for (int i = tid; i <= nwaves; i += 512) g_wstart[i] = wstart[i];
    if (tid == 0) g_nwaves = nwaves;
}

// ---------------- k7: wave-parallel neighbor-mean smoothing -----------------
#define SC_NEWOFF (573 * 32)
#define SC_DUMMY  (N_DRUG * 32)
#define SCAN_SMEM ((573 * 32 + N_DRUG * 32 + N_DRUG * 32 + 2 * N_DRUG \
                    + N_DRUG + (N_DRUG + 2)) * 4)

__global__ void k_scan(float* __restrict__ out,
                       const int* __restrict__ nbrI,
                       const int* __restrict__ nbrD,
                       const int* __restrict__ epoch) {
    if (epoch[0] <= 1) return;
    extern __shared__ __align__(16) char dyn[];
    float* fsh  = (float*)dyn;                         // old[573*32] ++ new[572*32]
    int*   idxS = (int*)(dyn + (573 * 32 + N_DRUG * 32) * 4);
    float* sc0  = (float*)((char*)idxS + N_DRUG * 32 * 4);
    float* sc1  = sc0 + N_DRUG;
    int*   orderS  = (int*)(sc1 + N_DRUG);
    int*   wstartS = orderS + N_DRUG;

    const int tid = threadIdx.x;               // 256
    const int cbase = blockIdx.x * 32;

    for (int idx = tid; idx < N_DRUG * 32; idx += 256) {
        int r = idx >> 5, c = idx & 31;
        fsh[idx] = out[(size_t)r * D + cbase + c];
    }
    if (tid < 32) fsh[SC_DUMMY + tid] = 0.f;

    for (int idx = tid; idx < N_DRUG * 32; idx += 256) {
        int r = idx >> 5, j = idx & 31;
        int dg = __ldg(&nbrD[r]);
        int p  = __ldg(&nbrI[idx]);
        int off;
        if (j < dg) off = (p << 5) + (p < r ? SC_NEWOFF : 0);
        else        off = SC_DUMMY;
        idxS[idx] = off;
    }
    for (int i = tid; i < N_DRUG; i += 256) {
        int dg = nbrD[i];
        sc0[i] = dg > 0 ? 0.5f : 1.0f;
        sc1[i] = dg > 0 ? 0.5f / (float)dg : 0.0f;
        orderS[i] = g_order[i];
    }
    const int nw = g_nwaves;
    for (int i = tid; i <= nw; i += 256) wstartS[i] = g_wstart[i];
    __syncthreads();

    const int wid = tid >> 5, lane = tid & 31;
    for (int w = 0; w < nw; w++) {
        const int s = wstartS[w], e = wstartS[w + 1];
        for (int slot = s + wid; slot < e; slot += 8) {
            const int i = orderS[slot];
            const int4* io4 = (const int4*)(idxS + (i << 5));
            float a0 = 0.f, a1 = 0.f, a2 = 0.f, a3 = 0.f;
            #pragma unroll
            for (int q = 0; q < 8; q++) {
                int4 c = io4[q];
                a0 += fsh[c.x + lane];
                a1 += fsh[c.y + lane];
                a2 += fsh[c.z + lane];
                a3 += fsh[c.w + lane];
            }
            float sm = (a0 + a1) + (a2 + a3);
            const int fi = (i << 5) + lane;
            fsh[SC_NEWOFF + fi] = sm * sc1[i] + fsh[fi] * sc0[i];
        }
        __syncthreads();
    }

    for (int idx = tid; idx < N_DRUG * 32; idx += 256) {
        int r = idx >> 5, c = idx & 31;
        out[(size_t)r * D + cbase + c] = fsh[SC_NEWOFF + idx];
    }
}

// ---------------- launch ----------------
extern "C" void kernel_launch(void* const* d_in, const int* in_sizes, int n_in,
                              void* d_out, int out_size) {
    const float* drugW = (const float*)d_in[0];
    const float* relaW = (const float*)d_in[1];
    const float* entW  = (const float*)d_in[2];
    const float* Wa    = (const float*)d_in[3];
    const float* linW  = (const float*)d_in[4];
    const float* linb  = (const float*)d_in[5];
    const float* gamma = (const float*)d_in[6];
    const float* beta  = (const float*)d_in[7];
    const int* names   = (const int*)d_in[8];
    const int* adjT    = (const int*)d_in[9];
    const int* adjR    = (const int*)d_in[10];
    const int* nbrI    = (const int*)d_in[11];
    const int* nbrD    = (const int*)d_in[12];
    const int* epoch   = (const int*)d_in[13];
    float* out = (float*)d_out;

    cudaFuncSetAttribute(k_scan, cudaFuncAttributeMaxDynamicSharedMemorySize,
                         SCAN_SMEM);
    cudaFuncSetAttribute(k_wave, cudaFuncAttributeMaxDynamicSharedMemorySize,
                         WAVE_SMEM);

    k_wave<<<1, 512, WAVE_SMEM>>>(nbrI, nbrD, epoch);
    k_qgemm<<<dim3(18, 8), 256>>>(drugW, Wa, names);
    k_attn<<<N_DRUG, 256>>>(relaW, entW, adjR, adjT);
    k_lin<<<dim3(18, 8), 256>>>(drugW, linW, linb, names);
    k_bnpart<<<NBN, D>>>();
    k_bnfin<<<1, D>>>();
    k_norm<<<N_DRUG, D>>>(gamma, beta, out);
    k_scan<<<16, 256, SCAN_SMEM>>>(out, nbrI, nbrD, epoch);
}

// round 7
// speedup vs baseline: 3.5735x; 1.0913x over previous
#include <cuda_runtime.h>
#include <math.h>

#define N_DRUG 572
#define D 512
#define KNBR 64
#define RREL 200
#define MAXDEG 32
#define EPS 1e-5f
#define NBN 64   // bn partial blocks

// ---------------- scratch (no allocs allowed) ----------------
__device__ float g_qpart[2 * N_DRUG * D];   // q k-split partials
__device__ float g_agg[N_DRUG * D];
__device__ float g_hpart[2 * N_DRUG * D];   // lin k-split partials
__device__ float g_h[N_DRUG * D];
__device__ float g_psum[NBN * D];
__device__ float g_psumsq[NBN * D];
__device__ float g_mean[D];
__device__ float g_rstd[D];
// wave schedule (computed by k_wave each call, deterministic)
__device__ int g_order[N_DRUG];
__device__ int g_wstart[N_DRUG + 2];
__device__ int g_nwaves;

// ======= K-split tiled GEMMs: BM=64, BN=64, BK=16, 256 thr, 4x4 tile ========
// grid (9, 8, 2): z = K-split. Balanced pipes: per k-step each thread does
// 2 x LDS.128 (A col + B col) feeding 16 FFMA. Double-buffered smem; global
// loads for chunk c+1 issued before computing chunk c.

// ---------------- k1: q partials = drug_e @ Wa[ksplit] ----------------
__global__ void k_qgemm(const float* __restrict__ drugW,
                        const float* __restrict__ Wa,
                        const int* __restrict__ names) {
    __shared__ float As[2][16][68];
    __shared__ float Bs[2][16][68];
    __shared__ int nm[64];
    const int tid = threadIdx.x;
    const int m0 = blockIdx.x * 64;
    const int n0 = blockIdx.y * 64;
    const int sp = blockIdx.z;           // K split
    const int kbase = sp * 256;
    if (tid < 64) {
        int r = m0 + tid;
        nm[tid] = r < N_DRUG ? names[r] : 0;
    }
    const int lk = tid & 15;        // A loader k
    const int lm = tid >> 4;        // A loader row base (4 passes of 16)
    const int bn = tid & 63;        // B loader col
    const int bk = tid >> 6;        // B loader k base (4 passes of 4)
    const int ty = tid >> 4, tx = tid & 15;
    __syncthreads();

    float acc[4][4] = {};

    #pragma unroll
    for (int p = 0; p < 4; p++) {
        int m = lm + p * 16;
        As[0][lk][m] = (m0 + m < N_DRUG)
                       ? drugW[(size_t)nm[m] * D + kbase + lk] : 0.f;
    }
    #pragma unroll
    for (int p = 0; p < 4; p++) {
        int kk = bk + p * 4;
        Bs[0][kk][bn] = Wa[(size_t)(kbase + kk) * D + n0 + bn];
    }
    __syncthreads();

    int buf = 0;
    const int NCH = 256 / 16;     // 16
    for (int ch = 0; ch < NCH; ch++) {
        float a_ld[4], b_ld[4];
        const bool has = (ch + 1 < NCH);
        if (has) {
            const int k1 = kbase + (ch + 1) * 16;
            #pragma unroll
            for (int p = 0; p < 4; p++) {
                int m = lm + p * 16;
                a_ld[p] = (m0 + m < N_DRUG)
                          ? drugW[(size_t)nm[m] * D + k1 + lk] : 0.f;
            }
            #pragma unroll
            for (int p = 0; p < 4; p++) {
                int kk = bk + p * 4;
                b_ld[p] = Wa[(size_t)(k1 + kk) * D + n0 + bn];
            }
        }
        #pragma unroll
        for (int kk = 0; kk < 16; kk++) {
            float4 a = *(const float4*)&As[buf][kk][4 * ty];
            float4 b = *(const float4*)&Bs[buf][kk][4 * tx];
            acc[0][0] += a.x * b.x; acc[0][1] += a.x * b.y;
            acc[0][2] += a.x * b.z; acc[0][3] += a.x * b.w;
            acc[1][0] += a.y * b.x; acc[1][1] += a.y * b.y;
            acc[1][2] += a.y * b.z; acc[1][3] += a.y * b.w;
            acc[2][0] += a.z * b.x; acc[2][1] += a.z * b.y;
            acc[2][2] += a.z * b.z; acc[2][3] += a.z * b.w;
            acc[3][0] += a.w * b.x; acc[3][1] += a.w * b.y;
            acc[3][2] += a.w * b.z; acc[3][3] += a.w * b.w;
        }
        if (has) {
            #pragma unroll
            for (int p = 0; p < 4; p++) As[buf ^ 1][lk][lm + p * 16] = a_ld[p];
            #pragma unroll
            for (int p = 0; p < 4; p++) Bs[buf ^ 1][bk + p * 4][bn] = b_ld[p];
        }
        __syncthreads();
        buf ^= 1;
    }

    float* dst = g_qpart + (size_t)sp * N_DRUG * D;
    #pragma unroll
    for (int r = 0; r < 4; r++) {
        int row = m0 + 4 * ty + r;
        if (row < N_DRUG) {
            float4 v = make_float4(acc[r][0], acc[r][1], acc[r][2], acc[r][3]);
            *(float4*)&dst[(size_t)row * D + n0 + 4 * tx] = v;
        }
    }
}

// ---------------- k3: h partials = concat(agg, drug_e)[ksplit] @ lin_W ------
__global__ void k_lin(const float* __restrict__ drugW,
                      const float* __restrict__ linW,
                      const int* __restrict__ names) {
    __shared__ float As[2][16][68];
    __shared__ float Bs[2][16][68];
    __shared__ int nm[64];
    const int tid = threadIdx.x;
    const int m0 = blockIdx.x * 64;
    const int n0 = blockIdx.y * 64;
    const int sp = blockIdx.z;           // 0: agg half (k<D), 1: drug half
    const int kbase = sp * D;
    if (tid < 64) {
        int r = m0 + tid;
        nm[tid] = r < N_DRUG ? names[r] : 0;
    }
    const int lk = tid & 15;
    const int lm = tid >> 4;
    const int bn = tid & 63;
    const int bk = tid >> 6;
    const int ty = tid >> 4, tx = tid & 15;
    __syncthreads();

    float acc[4][4] = {};

    #pragma unroll
    for (int p = 0; p < 4; p++) {
        int m = lm + p * 16;
        int row = m0 + m;
        float v = 0.f;
        if (row < N_DRUG)
            v = sp ? drugW[(size_t)nm[m] * D + lk]
                   : g_agg[(size_t)row * D + lk];
        As[0][lk][m] = v;
    }
    #pragma unroll
    for (int p = 0; p < 4; p++) {
        int kk = bk + p * 4;
        Bs[0][kk][bn] = linW[(size_t)(kbase + kk) * D + n0 + bn];
    }
    __syncthreads();

    int buf = 0;
    const int NCH = D / 16;      // 32
    for (int ch = 0; ch < NCH; ch++) {
        float a_ld[4], b_ld[4];
        const bool has = (ch + 1 < NCH);
        if (has) {
            const int kl = (ch + 1) * 16 + lk;
            #pragma unroll
            for (int p = 0; p < 4; p++) {
                int m = lm + p * 16;
                int row = m0 + m;
                float v = 0.f;
                if (row < N_DRUG)
                    v = sp ? drugW[(size_t)nm[m] * D + kl]
                           : g_agg[(size_t)row * D + kl];
                a_ld[p] = v;
            }
            const int kg = kbase + (ch + 1) * 16;
            #pragma unroll
            for (int p = 0; p < 4; p++) {
                int kk = bk + p * 4;
                b_ld[p] = linW[(size_t)(kg + kk) * D + n0 + bn];
            }
        }
        #pragma unroll
        for (int kk = 0; kk < 16; kk++) {
            float4 a = *(const float4*)&As[buf][kk][4 * ty];
            float4 b = *(const float4*)&Bs[buf][kk][4 * tx];
            acc[0][0] += a.x * b.x; acc[0][1] += a.x * b.y;
            acc[0][2] += a.x * b.z; acc[0][3] += a.x * b.w;
            acc[1][0] += a.y * b.x; acc[1][1] += a.y * b.y;
            acc[1][2] += a.y * b.z; acc[1][3] += a.y * b.w;
            acc[2][0] += a.z * b.x; acc[2][1] += a.z * b.y;
            acc[2][2] += a.z * b.z; acc[2][3] += a.z * b.w;
            acc[3][0] += a.w * b.x; acc[3][1] += a.w * b.y;
            acc[3][2] += a.w * b.z; acc[3][3] += a.w * b.w;
        }
        if (has) {
            #pragma unroll
            for (int p = 0; p < 4; p++) As[buf ^ 1][lk][lm + p * 16] = a_ld[p];
            #pragma unroll
            for (int p = 0; p < 4; p++) Bs[buf ^ 1][bk + p * 4][bn] = b_ld[p];
        }
        __syncthreads();
        buf ^= 1;
    }

    float* dst = g_hpart + (size_t)sp * N_DRUG * D;
    #pragma unroll
    for (int r = 0; r < 4; r++) {
        int row = m0 + 4 * ty + r;
        if (row < N_DRUG) {
            float4 v = make_float4(acc[r][0], acc[r][1], acc[r][2], acc[r][3]);
            *(float4*)&dst[(size_t)row * D + n0 + 4 * tx] = v;
        }
    }
}

// ---------------- k2: attention + softmax + gather-aggregate ----------------
__global__ void k_attn(const float* __restrict__ relaW,
                       const float* __restrict__ entW,
                       const int* __restrict__ adjR,
                       const int* __restrict__ adjT) {
    const int n = blockIdx.x;
    const int tid = threadIdx.x;           // 256 threads
    __shared__ float qsh[D];
    __shared__ float sc[KNBR];
    __shared__ float attn[KNBR];
    __shared__ int relS[KNBR], tailS[KNBR];

    if (tid < KNBR) {
        relS[tid]  = adjR[n * KNBR + tid];
        tailS[tid] = adjT[n * KNBR + tid];
    }
    // combine the two q k-split partials at load
    qsh[tid]       = g_qpart[(size_t)n * D + tid]
                   + g_qpart[(size_t)(N_DRUG + n) * D + tid];
    qsh[tid + 256] = g_qpart[(size_t)n * D + tid + 256]
                   + g_qpart[(size_t)(N_DRUG + n) * D + tid + 256];
    __syncthreads();

    const int w = tid >> 5, lane = tid & 31;
    #pragma unroll
    for (int kk = 0; kk < 8; kk++) {
        int k = w * 8 + kk;
        const float* base = relaW + (size_t)relS[k] * D;
        float p = 0.f;
        #pragma unroll
        for (int i = 0; i < 16; i++)
            p += qsh[lane + 32 * i] * base[lane + 32 * i];
        #pragma unroll
        for (int off = 16; off; off >>= 1)
            p += __shfl_xor_sync(0xffffffffu, p, off);
        if (lane == 0) sc[k] = p * 0.044194173824159216f;  // 1/sqrt(512)
    }
    __syncthreads();

    if (w == 0) {
        float v0 = sc[lane], v1 = sc[lane + 32];
        float m = fmaxf(v0, v1);
        #pragma unroll
        for (int off = 16; off; off >>= 1)
            m = fmaxf(m, __shfl_xor_sync(0xffffffffu, m, off));
        float e0 = expf(v0 - m), e1 = expf(v1 - m);
        float s = e0 + e1;
        #pragma unroll
        for (int off = 16; off; off >>= 1)
            s += __shfl_xor_sync(0xffffffffu, s, off);
        float inv = 1.f / s;
        attn[lane] = e0 * inv;
        attn[lane + 32] = e1 * inv;
    }
    __syncthreads();

    float a0 = 0.f, a1 = 0.f;
    const int d = tid;
    #pragma unroll 8
    for (int k = 0; k < KNBR; k++) {
        const float* er = entW + (size_t)tailS[k] * D;
        float a = attn[k];
        a0 += a * er[d];
        a1 += a * er[d + 256];
    }
    g_agg[(size_t)n * D + d]       = a0;
    g_agg[(size_t)n * D + d + 256] = a1;
}

// ---------------- k4: combine lin partials + bias + relu + BN stats ---------
__global__ void k_bnpart(const float* __restrict__ linb) {
    const int b = blockIdx.x;       // 64 blocks
    const int d = threadIdx.x;      // 512 threads
    const int r0 = b * 9;
    const int r1 = min(N_DRUG, r0 + 9);
    const float bb = linb[d];
    float s = 0.f, sq = 0.f;
    for (int r = r0; r < r1; r++) {
        float v = g_hpart[(size_t)r * D + d]
                + g_hpart[(size_t)(N_DRUG + r) * D + d] + bb;
        v = v > 0.f ? v : 0.f;
        g_h[(size_t)r * D + d] = v;
        s += v;
        sq += v * v;
    }
    g_psum[b * D + d] = s;
    g_psumsq[b * D + d] = sq;
}

__global__ void k_bnfin() {
    const int d = threadIdx.x;
    float s = 0.f, sq = 0.f;
    #pragma unroll
    for (int b = 0; b < NBN; b++) {
        s  += g_psum[b * D + d];
        sq += g_psumsq[b * D + d];
    }
    const float invN = 1.f / (float)N_DRUG;
    float mean = s * invN;
    float var = sq * invN - mean * mean;
    g_mean[d] = mean;
    g_rstd[d] = rsqrtf(var + EPS);
}

__global__ void k_norm(const float* __restrict__ gamma,
                       const float* __restrict__ beta,
                       float* __restrict__ out) {
    const int n = blockIdx.x;
    const int d = threadIdx.x;
    float v = g_h[(size_t)n * D + d];
    out[(size_t)n * D + d] = (v - g_mean[d]) * g_rstd[d] * gamma[d] + beta[d];
}

// ---------------- k_wave: topological wave schedule (Kahn BFS) --------------
#define WAVE_SMEM ((N_DRUG * 4 /*indeg,scnt,cur,order*/ \
                   + (N_DRUG + 1) /*soff*/ + (N_DRUG + 2) /*wstart*/ \
                   + N_DRUG * MAXDEG /*succ*/ + 4 /*counters*/) * 4)

__global__ void k_wave(const int* __restrict__ nbrI,
                       const int* __restrict__ nbrD,
                       const int* __restrict__ epoch) {
    if (epoch[0] <= 1) return;
    extern __shared__ int ws[];
    int* indeg  = ws;                          // [572]
    int* scnt   = indeg + N_DRUG;              // [572]
    int* cur    = scnt + N_DRUG;               // [572]
    int* order  = cur + N_DRUG;                // [572]
    int* soff   = order + N_DRUG;              // [573]
    int* wstart = soff + N_DRUG + 1;           // [574]
    int* succ   = wstart + N_DRUG + 2;         // [572*32]
    int* counters = succ + N_DRUG * MAXDEG;    // [4]

    const int tid = threadIdx.x;               // 512
    const int wid = tid >> 5, lane = tid & 31;

    for (int i = tid; i < N_DRUG; i += 512) { indeg[i] = 0; scnt[i] = 0; }
    if (tid == 0) counters[0] = 0;
    __syncthreads();

    for (int i = tid; i < N_DRUG; i += 512) {
        int dg = nbrD[i];
        int cnt = 0;
        for (int j = 0; j < dg; j++) {
            int p = nbrI[i * MAXDEG + j];
            if (p < i) { cnt++; atomicAdd(&scnt[p], 1); }
        }
        indeg[i] = cnt;
    }
    __syncthreads();

    if (wid == 0) {
        const int CH = 18;
        int lo = lane * CH, hi = min(N_DRUG, lo + CH);
        int s = 0;
        for (int k = lo; k < hi; k++) s += scnt[k];
        int v = s;
        #pragma unroll
        for (int off = 1; off < 32; off <<= 1) {
            int t = __shfl_up_sync(0xffffffffu, v, off);
            if (lane >= off) v += t;
        }
        int excl = v - s;
        int run = excl;
        for (int k = lo; k < hi; k++) {
            soff[k] = run; cur[k] = run; run += scnt[k];
        }
        if (lane == 31) soff[N_DRUG] = run;
    }
    __syncthreads();

    for (int i = tid; i < N_DRUG; i += 512) {
        int dg = nbrD[i];
        for (int j = 0; j < dg; j++) {
            int p = nbrI[i * MAXDEG + j];
            if (p < i) {
                int pos = atomicAdd(&cur[p], 1);
                succ[pos] = i;
            }
        }
    }
    __syncthreads();

    for (int i = tid; i < N_DRUG; i += 512)
        if (indeg[i] == 0) {
            int pos = atomicAdd(&counters[0], 1);
            order[pos] = i;
        }
    __syncthreads();

    int wbase = 0;
    int placed = counters[0];
    int wcount = placed;
    int w = 0;
    if (tid == 0) { wstart[0] = 0; wstart[1] = placed; }
    __syncthreads();

    while (placed < N_DRUG && wcount > 0) {
        for (int slot = wbase + wid; slot < wbase + wcount; slot += 16) {
            int n = order[slot];
            int s0 = soff[n], s1 = soff[n + 1];
            for (int e = s0 + lane; e < s1; e += 32) {
                int sn = succ[e];
                if (atomicSub(&indeg[sn], 1) == 1) {
                    int pos = atomicAdd(&counters[0], 1);
                    order[pos] = sn;
                }
            }
        }
        __syncthreads();
        wbase += wcount;
        int total = counters[0];
        wcount = total - placed;
        placed = total;
        w++;
        if (tid == 0) wstart[w + 1] = total;
        __syncthreads();
    }

    const int nwaves = w + 1;
    for (int i = tid; i < N_DRUG; i += 512) g_order[i] = order[i];
    for (int i = tid; i <= nwaves; i += 512) g_wstart[i] = wstart[i];
    if (tid == 0) g_nwaves = nwaves;
}

// ---------------- k7: wave-parallel neighbor-mean smoothing -----------------
#define SC_NEWOFF (573 * 32)
#define SC_DUMMY  (N_DRUG * 32)
#define SCAN_SMEM ((573 * 32 + N_DRUG * 32 + N_DRUG * 32 + 2 * N_DRUG \
                    + N_DRUG + (N_DRUG + 2)) * 4)

__global__ void k_scan(float* __restrict__ out,
                       const int* __restrict__ nbrI,
                       const int* __restrict__ nbrD,
                       const int* __restrict__ epoch) {
    if (epoch[0] <= 1) return;
    extern __shared__ __align__(16) char dyn[];
    float* fsh  = (float*)dyn;                         // old[573*32] ++ new[572*32]
    int*   idxS = (int*)(dyn + (573 * 32 + N_DRUG * 32) * 4);
    float* sc0  = (float*)((char*)idxS + N_DRUG * 32 * 4);
    float* sc1  = sc0 + N_DRUG;
    int*   orderS  = (int*)(sc1 + N_DRUG);
    int*   wstartS = orderS + N_DRUG;

    const int tid = threadIdx.x;               // 256
    const int cbase = blockIdx.x * 32;

    for (int idx = tid; idx < N_DRUG * 32; idx += 256) {
        int r = idx >> 5, c = idx & 31;
        fsh[idx] = out[(size_t)r * D + cbase + c];
    }
    if (tid < 32) fsh[SC_DUMMY + tid] = 0.f;

    for (int idx = tid; idx < N_DRUG * 32; idx += 256) {
        int r = idx >> 5, j = idx & 31;
        int dg = __ldg(&nbrD[r]);
        int p  = __ldg(&nbrI[idx]);
        int off;
        if (j < dg) off = (p << 5) + (p < r ? SC_NEWOFF : 0);
        else        off = SC_DUMMY;
        idxS[idx] = off;
    }
    for (int i = tid; i < N_DRUG; i += 256) {
        int dg = nbrD[i];
        sc0[i] = dg > 0 ? 0.5f : 1.0f;
        sc1[i] = dg > 0 ? 0.5f / (float)dg : 0.0f;
        orderS[i] = g_order[i];
    }
    const int nw = g_nwaves;
    for (int i = tid; i <= nw; i += 256) wstartS[i] = g_wstart[i];
    __syncthreads();

    const int wid = tid >> 5, lane = tid & 31;
    for (int w = 0; w < nw; w++) {
        const int s = wstartS[w], e = wstartS[w + 1];
        for (int slot = s + wid; slot < e; slot += 8) {
            const int i = orderS[slot];
            const int4* io4 = (const int4*)(idxS + (i << 5));
            float a0 = 0.f, a1 = 0.f, a2 = 0.f, a3 = 0.f;
            #pragma unroll
            for (int q = 0; q < 8; q++) {
                int4 c = io4[q];
                a0 += fsh[c.x + lane];
                a1 += fsh[c.y + lane];
                a2 += fsh[c.z + lane];
                a3 += fsh[c.w + lane];
            }
            float sm = (a0 + a1) + (a2 + a3);
            const int fi = (i << 5) + lane;
            fsh[SC_NEWOFF + fi] = sm * sc1[i] + fsh[fi] * sc0[i];
        }
        __syncthreads();
    }

    for (int idx = tid; idx < N_DRUG * 32; idx += 256) {
        int r = idx >> 5, c = idx & 31;
        out[(size_t)r * D + cbase + c] = fsh[SC_NEWOFF + idx];
    }
}

// ---------------- launch ----------------
extern "C" void kernel_launch(void* const* d_in, const int* in_sizes, int n_in,
                              void* d_out, int out_size) {
    const float* drugW = (const float*)d_in[0];
    const float* relaW = (const float*)d_in[1];
    const float* entW  = (const float*)d_in[2];
    const float* Wa    = (const float*)d_in[3];
    const float* linW  = (const float*)d_in[4];
    const float* linb  = (const float*)d_in[5];
    const float* gamma = (const float*)d_in[6];
    const float* beta  = (const float*)d_in[7];
    const int* names   = (const int*)d_in[8];
    const int* adjT    = (const int*)d_in[9];
    const int* adjR    = (const int*)d_in[10];
    const int* nbrI    = (const int*)d_in[11];
    const int* nbrD    = (const int*)d_in[12];
    const int* epoch   = (const int*)d_in[13];
    float* out = (float*)d_out;

    cudaFuncSetAttribute(k_scan, cudaFuncAttributeMaxDynamicSharedMemorySize,
                         SCAN_SMEM);
    cudaFuncSetAttribute(k_wave, cudaFuncAttributeMaxDynamicSharedMemorySize,
                         WAVE_SMEM);

    k_wave<<<1, 512, WAVE_SMEM>>>(nbrI, nbrD, epoch);
    k_qgemm<<<dim3(9, 8, 2), 256>>>(drugW, Wa, names);
    k_attn<<<N_DRUG, 256>>>(relaW, entW, adjR, adjT);
    k_lin<<<dim3(9, 8, 2), 256>>>(drugW, linW, names);
    k_bnpart<<<NBN, D>>>(linb);
    k_bnfin<<<1, D>>>();
    k_norm<<<N_DRUG, D>>>(gamma, beta, out);
    k_scan<<<16, 256, SCAN_SMEM>>>(out, nbrI, nbrD, epoch);
}

// round 9
// speedup vs baseline: 3.7568x; 1.0513x over previous
#include <cuda_runtime.h>
#include <math.h>

#define N_DRUG 572
#define D 512
#define KNBR 64
#define RREL 200
#define MAXDEG 32
#define EPS 1e-5f
#define NBN 64   // bn partial blocks
#define KSPL 4   // K splits for GEMMs

// ---------------- scratch (no allocs allowed) ----------------
__device__ float g_qpart[KSPL * N_DRUG * D];
__device__ float g_agg[N_DRUG * D];
__device__ float g_hpart[KSPL * N_DRUG * D];
__device__ float g_h[N_DRUG * D];
__device__ float g_psum[NBN * D];
__device__ float g_psumsq[NBN * D];
__device__ float g_mean[D];
__device__ float g_rstd[D];
// wave schedule (computed by k_wave each call, deterministic)
__device__ int g_order[N_DRUG];
__device__ int g_wstart[N_DRUG + 2];
__device__ int g_nwaves;

// ======= K-split tiled GEMMs: BM=64, BN=64, BK=16, 256 thr, 4x4 tile ========
// grid (9, 8, 4): z = K-split -> 288 blocks = 2 blocks/SM (16 warps/SM).

// ---------------- k1: q partials = drug_e @ Wa[ksplit] ----------------
__global__ void k_qgemm(const float* __restrict__ drugW,
                        const float* __restrict__ Wa,
                        const int* __restrict__ names) {
    __shared__ float As[2][16][68];
    __shared__ float Bs[2][16][68];
    __shared__ int nm[64];
    const int tid = threadIdx.x;
    const int m0 = blockIdx.x * 64;
    const int n0 = blockIdx.y * 64;
    const int sp = blockIdx.z;           // K split
    const int kbase = sp * (D / KSPL);   // 128 per split
    if (tid < 64) {
        int r = m0 + tid;
        nm[tid] = r < N_DRUG ? names[r] : 0;
    }
    const int lk = tid & 15;
    const int lm = tid >> 4;
    const int bn = tid & 63;
    const int bk = tid >> 6;
    const int ty = tid >> 4, tx = tid & 15;
    __syncthreads();

    float acc[4][4] = {};

    #pragma unroll
    for (int p = 0; p < 4; p++) {
        int m = lm + p * 16;
        As[0][lk][m] = (m0 + m < N_DRUG)
                       ? drugW[(size_t)nm[m] * D + kbase + lk] : 0.f;
    }
    #pragma unroll
    for (int p = 0; p < 4; p++) {
        int kk = bk + p * 4;
        Bs[0][kk][bn] = Wa[(size_t)(kbase + kk) * D + n0 + bn];
    }
    __syncthreads();

    int buf = 0;
    const int NCH = (D / KSPL) / 16;     // 8
    for (int ch = 0; ch < NCH; ch++) {
        float a_ld[4], b_ld[4];
        const bool has = (ch + 1 < NCH);
        if (has) {
            const int k1 = kbase + (ch + 1) * 16;
            #pragma unroll
            for (int p = 0; p < 4; p++) {
                int m = lm + p * 16;
                a_ld[p] = (m0 + m < N_DRUG)
                          ? drugW[(size_t)nm[m] * D + k1 + lk] : 0.f;
            }
            #pragma unroll
            for (int p = 0; p < 4; p++) {
                int kk = bk + p * 4;
                b_ld[p] = Wa[(size_t)(k1 + kk) * D + n0 + bn];
            }
        }
        #pragma unroll
        for (int kk = 0; kk < 16; kk++) {
            float4 a = *(const float4*)&As[buf][kk][4 * ty];
            float4 b = *(const float4*)&Bs[buf][kk][4 * tx];
            acc[0][0] += a.x * b.x; acc[0][1] += a.x * b.y;
            acc[0][2] += a.x * b.z; acc[0][3] += a.x * b.w;
            acc[1][0] += a.y * b.x; acc[1][1] += a.y * b.y;
            acc[1][2] += a.y * b.z; acc[1][3] += a.y * b.w;
            acc[2][0] += a.z * b.x; acc[2][1] += a.z * b.y;
            acc[2][2] += a.z * b.z; acc[2][3] += a.z * b.w;
            acc[3][0] += a.w * b.x; acc[3][1] += a.w * b.y;
            acc[3][2] += a.w * b.z; acc[3][3] += a.w * b.w;
        }
        if (has) {
            #pragma unroll
            for (int p = 0; p < 4; p++) As[buf ^ 1][lk][lm + p * 16] = a_ld[p];
            #pragma unroll
            for (int p = 0; p < 4; p++) Bs[buf ^ 1][bk + p * 4][bn] = b_ld[p];
        }
        __syncthreads();
        buf ^= 1;
    }

    float* dst = g_qpart + (size_t)sp * N_DRUG * D;
    #pragma unroll
    for (int r = 0; r < 4; r++) {
        int row = m0 + 4 * ty + r;
        if (row < N_DRUG) {
            float4 v = make_float4(acc[r][0], acc[r][1], acc[r][2], acc[r][3]);
            *(float4*)&dst[(size_t)row * D + n0 + 4 * tx] = v;
        }
    }
}

// ---------------- k3: h partials = concat(agg, drug_e)[ksplit] @ lin_W ------
__global__ void k_lin(const float* __restrict__ drugW,
                      const float* __restrict__ linW,
                      const int* __restrict__ names) {
    __shared__ float As[2][16][68];
    __shared__ float Bs[2][16][68];
    __shared__ int nm[64];
    const int tid = threadIdx.x;
    const int m0 = blockIdx.x * 64;
    const int n0 = blockIdx.y * 64;
    const int sp = blockIdx.z;             // 0,1: agg halves; 2,3: drug halves
    const bool useDrug = sp >= 2;
    const int kA = (sp & 1) * 256;         // offset within A source
    const int kB = sp * 256;               // offset within linW rows
    if (tid < 64) {
        int r = m0 + tid;
        nm[tid] = r < N_DRUG ? names[r] : 0;
    }
    const int lk = tid & 15;
    const int lm = tid >> 4;
    const int bn = tid & 63;
    const int bk = tid >> 6;
    const int ty = tid >> 4, tx = tid & 15;
    __syncthreads();

    float acc[4][4] = {};

    #pragma unroll
    for (int p = 0; p < 4; p++) {
        int m = lm + p * 16;
        int row = m0 + m;
        float v = 0.f;
        if (row < N_DRUG)
            v = useDrug ? drugW[(size_t)nm[m] * D + kA + lk]
                        : g_agg[(size_t)row * D + kA + lk];
        As[0][lk][m] = v;
    }
    #pragma unroll
    for (int p = 0; p < 4; p++) {
        int kk = bk + p * 4;
        Bs[0][kk][bn] = linW[(size_t)(kB + kk) * D + n0 + bn];
    }
    __syncthreads();

    int buf = 0;
    const int NCH = 256 / 16;      // 16
    for (int ch = 0; ch < NCH; ch++) {
        float a_ld[4], b_ld[4];
        const bool has = (ch + 1 < NCH);
        if (has) {
            const int kl = kA + (ch + 1) * 16 + lk;
            #pragma unroll
            for (int p = 0; p < 4; p++) {
                int m = lm + p * 16;
                int row = m0 + m;
                float v = 0.f;
                if (row < N_DRUG)
                    v = useDrug ? drugW[(size_t)nm[m] * D + kl]
                                : g_agg[(size_t)row * D + kl];
                a_ld[p] = v;
            }
            const int kg = kB + (ch + 1) * 16;
            #pragma unroll
            for (int p = 0; p < 4; p++) {
                int kk = bk + p * 4;
                b_ld[p] = linW[(size_t)(kg + kk) * D + n0 + bn];
            }
        }
        #pragma unroll
        for (int kk = 0; kk < 16; kk++) {
            float4 a = *(const float4*)&As[buf][kk][4 * ty];
            float4 b = *(const float4*)&Bs[buf][kk][4 * tx];
            acc[0][0] += a.x * b.x; acc[0][1] += a.x * b.y;
            acc[0][2] += a.x * b.z; acc[0][3] += a.x * b.w;
            acc[1][0] += a.y * b.x; acc[1][1] += a.y * b.y;
            acc[1][2] += a.y * b.z; acc[1][3] += a.y * b.w;
            acc[2][0] += a.z * b.x; acc[2][1] += a.z * b.y;
            acc[2][2] += a.z * b.z; acc[2][3] += a.z * b.w;
            acc[3][0] += a.w * b.x; acc[3][1] += a.w * b.y;
            acc[3][2] += a.w * b.z; acc[3][3] += a.w * b.w;
        }
        if (has) {
            #pragma unroll
            for (int p = 0; p < 4; p++) As[buf ^ 1][lk][lm + p * 16] = a_ld[p];
            #pragma unroll
            for (int p = 0; p < 4; p++) Bs[buf ^ 1][bk + p * 4][bn] = b_ld[p];
        }
        __syncthreads();
        buf ^= 1;
    }

    float* dst = g_hpart + (size_t)sp * N_DRUG * D;
    #pragma unroll
    for (int r = 0; r < 4; r++) {
        int row = m0 + 4 * ty + r;
        if (row < N_DRUG) {
            float4 v = make_float4(acc[r][0], acc[r][1], acc[r][2], acc[r][3]);
            *(float4*)&dst[(size_t)row * D + n0 + 4 * tx] = v;
        }
    }
}

// ---------------- k2: attention + softmax + gather-aggregate ----------------
__global__ void k_attn(const float* __restrict__ relaW,
                       const float* __restrict__ entW,
                       const int* __restrict__ adjR,
                       const int* __restrict__ adjT) {
    const int n = blockIdx.x;
    const int tid = threadIdx.x;           // 256 threads
    __shared__ float qsh[D];
    __shared__ float sc[KNBR];
    __shared__ float attn[KNBR];
    __shared__ int relS[KNBR], tailS[KNBR];

    if (tid < KNBR) {
        relS[tid]  = adjR[n * KNBR + tid];
        tailS[tid] = adjT[n * KNBR + tid];
    }
    // combine the 4 q k-split partials at load
    #pragma unroll
    for (int h = 0; h < 2; h++) {
        int d = tid + h * 256;
        float v = 0.f;
        #pragma unroll
        for (int s = 0; s < KSPL; s++)
            v += g_qpart[(size_t)(s * N_DRUG + n) * D + d];
        qsh[d] = v;
    }
    __syncthreads();

    const int w = tid >> 5, lane = tid & 31;
    #pragma unroll
    for (int kk = 0; kk < 8; kk++) {
        int k = w * 8 + kk;
        const float* base = relaW + (size_t)relS[k] * D;
        float p = 0.f;
        #pragma unroll
        for (int i = 0; i < 16; i++)
            p += qsh[lane + 32 * i] * base[lane + 32 * i];
        #pragma unroll
        for (int off = 16; off; off >>= 1)
            p += __shfl_xor_sync(0xffffffffu, p, off);
        if (lane == 0) sc[k] = p * 0.044194173824159216f;  // 1/sqrt(512)
    }
    __syncthreads();

    if (w == 0) {
        float v0 = sc[lane], v1 = sc[lane + 32];
        float m = fmaxf(v0, v1);
        #pragma unroll
        for (int off = 16; off; off >>= 1)
            m = fmaxf(m, __shfl_xor_sync(0xffffffffu, m, off));
        float e0 = expf(v0 - m), e1 = expf(v1 - m);
        float s = e0 + e1;
        #pragma unroll
        for (int off = 16; off; off >>= 1)
            s += __shfl_xor_sync(0xffffffffu, s, off);
        float inv = 1.f / s;
        attn[lane] = e0 * inv;
        attn[lane + 32] = e1 * inv;
    }
    __syncthreads();

    float a0 = 0.f, a1 = 0.f;
    const int d = tid;
    #pragma unroll 8
    for (int k = 0; k < KNBR; k++) {
        const float* er = entW + (size_t)tailS[k] * D;
        float a = attn[k];
        a0 += a * er[d];
        a1 += a * er[d + 256];
    }
    g_agg[(size_t)n * D + d]       = a0;
    g_agg[(size_t)n * D + d + 256] = a1;
}

// ---------------- k4: combine lin partials + bias + relu + BN stats ---------
__global__ void k_bnpart(const float* __restrict__ linb) {
    const int b = blockIdx.x;       // 64 blocks
    const int d = threadIdx.x;      // 512 threads
    const int r0 = b * 9;
    const int r1 = min(N_DRUG, r0 + 9);
    const float bb = linb[d];
    float s = 0.f, sq = 0.f;
    for (int r = r0; r < r1; r++) {
        float v = bb;
        #pragma unroll
        for (int sp = 0; sp < KSPL; sp++)
            v += g_hpart[(size_t)(sp * N_DRUG + r) * D + d];
        v = v > 0.f ? v : 0.f;
        g_h[(size_t)r * D + d] = v;
        s += v;
        sq += v * v;
    }
    g_psum[b * D + d] = s;
    g_psumsq[b * D + d] = sq;
}

__global__ void k_bnfin() {
    const int d = threadIdx.x;
    float s = 0.f, sq = 0.f;
    #pragma unroll
    for (int b = 0; b < NBN; b++) {
        s  += g_psum[b * D + d];
        sq += g_psumsq[b * D + d];
    }
    const float invN = 1.f / (float)N_DRUG;
    float mean = s * invN;
    float var = sq * invN - mean * mean;
    g_mean[d] = mean;
    g_rstd[d] = rsqrtf(var + EPS);
}

__global__ void k_norm(const float* __restrict__ gamma,
                       const float* __restrict__ beta,
                       float* __restrict__ out) {
    const int n = blockIdx.x;
    const int d = threadIdx.x;
    float v = g_h[(size_t)n * D + d];
    out[(size_t)n * D + d] = (v - g_mean[d]) * g_rstd[d] * gamma[d] + beta[d];
}

// ---------------- k_wave: topological wave schedule (Kahn BFS) --------------
#define WAVE_SMEM ((N_DRUG * 4 /*indeg,scnt,cur,order*/ \
                   + (N_DRUG + 1) /*soff*/ + (N_DRUG + 2) /*wstart*/ \
                   + N_DRUG * MAXDEG /*succ*/ + 4 /*counters*/) * 4)

__global__ void k_wave(const int* __restrict__ nbrI,
                       const int* __restrict__ nbrD,
                       const int* __restrict__ epoch) {
    if (epoch[0] <= 1) return;
    extern __shared__ int ws[];
    int* indeg  = ws;                          // [572]
    int* scnt   = indeg + N_DRUG;              // [572]
    int* cur    = scnt + N_DRUG;               // [572]
    int* order  = cur + N_DRUG;                // [572]
    int* soff   = order + N_DRUG;              // [573]
    int* wstart = soff + N_DRUG + 1;           // [574]
    int* succ   = wstart + N_DRUG + 2;         // [572*32]
    int* counters = succ + N_DRUG * MAXDEG;    // [4]

    const int tid = threadIdx.x;               // 512
    const int wid = tid >> 5, lane = tid & 31;

    for (int i = tid; i < N_DRUG; i += 512) { indeg[i] = 0; scnt[i] = 0; }
    if (tid == 0) counters[0] = 0;
    __syncthreads();

    for (int i = tid; i < N_DRUG; i += 512) {
        int dg = nbrD[i];
        int cnt = 0;
        for (int j = 0; j < dg; j++) {
            int p = nbrI[i * MAXDEG + j];
            if (p < i) { cnt++; atomicAdd(&scnt[p], 1); }
        }
        indeg[i] = cnt;
    }
    __syncthreads();

    if (wid == 0) {
        const int CH = 18;
        int lo = lane * CH, hi = min(N_DRUG, lo + CH);
        int s = 0;
        for (int k = lo; k < hi; k++) s += scnt[k];
        int v = s;
        #pragma unroll
        for (int off = 1; off < 32; off <<= 1) {
            int t = __shfl_up_sync(0xffffffffu, v, off);
            if (lane >= off) v += t;
        }
        int excl = v - s;
        int run = excl;
        for (int k = lo; k < hi; k++) {
            soff[k] = run; cur[k] = run; run += scnt[k];
        }
        if (lane == 31) soff[N_DRUG] = run;
    }
    __syncthreads();

    for (int i = tid; i < N_DRUG; i += 512) {
        int dg = nbrD[i];
        for (int j = 0; j < dg; j++) {
            int p = nbrI[i * MAXDEG + j];
            if (p < i) {
                int pos = atomicAdd(&cur[p], 1);
                succ[pos] = i;
            }
        }
    }
    __syncthreads();

    for (int i = tid; i < N_DRUG; i += 512)
        if (indeg[i] == 0) {
            int pos = atomicAdd(&counters[0], 1);
            order[pos] = i;
        }
    __syncthreads();

    int wbase = 0;
    int placed = counters[0];
    int wcount = placed;
    int w = 0;
    if (tid == 0) { wstart[0] = 0; wstart[1] = placed; }
    __syncthreads();

    while (placed < N_DRUG && wcount > 0) {
        for (int slot = wbase + wid; slot < wbase + wcount; slot += 16) {
            int n = order[slot];
            int s0 = soff[n], s1 = soff[n + 1];
            for (int e = s0 + lane; e < s1; e += 32) {
                int sn = succ[e];
                if (atomicSub(&indeg[sn], 1) == 1) {
                    int pos = atomicAdd(&counters[0], 1);
                    order[pos] = sn;
                }
            }
        }
        __syncthreads();
        wbase += wcount;
        int total = counters[0];
        wcount = total - placed;
        placed = total;
        w++;
        if (tid == 0) wstart[w + 1] = total;
        __syncthreads();
    }

    const int nwaves = w + 1;
    for (int i = tid; i < N_DRUG; i += 512) g_order[i] = order[i];
    for (int i = tid; i <= nwaves; i += 512) g_wstart[i] = wstart[i];
    if (tid == 0) g_nwaves = nwaves;
}

// ---------------- k7: wave-parallel neighbor-mean smoothing -----------------
#define SC_NEWOFF (573 * 32)
#define SC_DUMMY  (N_DRUG * 32)
#define SCAN_SMEM ((573 * 32 + N_DRUG * 32 + N_DRUG * 32 + 2 * N_DRUG \
                    + N_DRUG + (N_DRUG + 2)) * 4)

__global__ void k_scan(float* __restrict__ out,
                       const int* __restrict__ nbrI,
                       const int* __restrict__ nbrD,
                       const int* __restrict__ epoch) {
    if (epoch[0] <= 1) return;
    extern __shared__ __align__(16) char dyn[];
    float* fsh  = (float*)dyn;                         // old[573*32] ++ new[572*32]
    int*   idxS = (int*)(dyn + (573 * 32 + N_DRUG * 32) * 4);
    float* sc0  = (float*)((char*)idxS + N_DRUG * 32 * 4);
    float* sc1  = sc0 + N_DRUG;
    int*   orderS  = (int*)(sc1 + N_DRUG);
    int*   wstartS = orderS + N_DRUG;

    const int tid = threadIdx.x;               // 256
    const int cbase = blockIdx.x * 32;

    for (int idx = tid; idx < N_DRUG * 32; idx += 256) {
        int r = idx >> 5, c = idx & 31;
        fsh[idx] = out[(size_t)r * D + cbase + c];
    }
    if (tid < 32) fsh[SC_DUMMY + tid] = 0.f;

    for (int idx = tid; idx < N_DRUG * 32; idx += 256) {
        int r = idx >> 5, j = idx & 31;
        int dg = __ldg(&nbrD[r]);
        int p  = __ldg(&nbrI[idx]);
        int off;
        if (j < dg) off = (p << 5) + (p < r ? SC_NEWOFF : 0);
        else        off = SC_DUMMY;
        idxS[idx] = off;
    }
    for (int i = tid; i < N_DRUG; i += 256) {
        int dg = nbrD[i];
        sc0[i] = dg > 0 ? 0.5f : 1.0f;
        sc1[i] = dg > 0 ? 0.5f / (float)dg : 0.0f;
        orderS[i] = g_order[i];
    }
    const int nw = g_nwaves;
    for (int i = tid; i <= nw; i += 256) wstartS[i] = g_wstart[i];
    __syncthreads();

    const int wid = tid >> 5, lane = tid & 31;
    for (int w = 0; w < nw; w++) {
        const int s = wstartS[w], e = wstartS[w + 1];
        for (int slot = s + wid; slot < e; slot += 8) {
            const int i = orderS[slot];
            const int4* io4 = (const int4*)(idxS + (i << 5));
            float a0 = 0.f, a1 = 0.f, a2 = 0.f, a3 = 0.f;
            #pragma unroll
            for (int q = 0; q < 8; q++) {
                int4 c = io4[q];
                a0 += fsh[c.x + lane];
                a1 += fsh[c.y + lane];
                a2 += fsh[c.z + lane];
                a3 += fsh[c.w + lane];
            }
            float sm = (a0 + a1) + (a2 + a3);
            const int fi = (i << 5) + lane;
            fsh[SC_NEWOFF + fi] = sm * sc1[i] + fsh[fi] * sc0[i];
        }
        __syncthreads();
    }

    for (int idx = tid; idx < N_DRUG * 32; idx += 256) {
        int r = idx >> 5, c = idx & 31;
        out[(size_t)r * D + cbase + c] = fsh[SC_NEWOFF + idx];
    }
}

// ---------------- launch ----------------
extern "C" void kernel_launch(void* const* d_in, const int* in_sizes, int n_in,
                              void* d_out, int out_size) {
    const float* drugW = (const float*)d_in[0];
    const float* relaW = (const float*)d_in[1];
    const float* entW  = (const float*)d_in[2];
    const float* Wa    = (const float*)d_in[3];
    const float* linW  = (const float*)d_in[4];
    const float* linb  = (const float*)d_in[5];
    const float* gamma = (const float*)d_in[6];
    const float* beta  = (const float*)d_in[7];
    const int* names   = (const int*)d_in[8];
    const int* adjT    = (const int*)d_in[9];
    const int* adjR    = (const int*)d_in[10];
    const int* nbrI    = (const int*)d_in[11];
    const int* nbrD    = (const int*)d_in[12];
    const int* epoch   = (const int*)d_in[13];
    float* out = (float*)d_out;

    cudaFuncSetAttribute(k_scan, cudaFuncAttributeMaxDynamicSharedMemorySize,
                         SCAN_SMEM);
    cudaFuncSetAttribute(k_wave, cudaFuncAttributeMaxDynamicSharedMemorySize,
                         WAVE_SMEM);

    k_wave<<<1, 512, WAVE_SMEM>>>(nbrI, nbrD, epoch);
    k_qgemm<<<dim3(9, 8, KSPL), 256>>>(drugW, Wa, names);
    k_attn<<<N_DRUG, 256>>>(relaW, entW, adjR, adjT);
    k_lin<<<dim3(9, 8, KSPL), 256>>>(drugW, linW, names);
    k_bnpart<<<NBN, D>>>(linb);
    k_bnfin<<<1, D>>>();
    k_norm<<<N_DRUG, D>>>(gamma, beta, out);
    k_scan<<<16, 256, SCAN_SMEM>>>(out, nbrI, nbrD, epoch);
}

// round 10
// speedup vs baseline: 4.4561x; 1.1861x over previous
#include <cuda_runtime.h>
#include <math.h>

#define N_DRUG 572
#define D 512
#define KNBR 64
#define RREL 200
#define MAXDEG 32
#define EPS 1e-5f
#define NBN 64   // bn partial blocks
#define KSPL 4   // K splits for GEMMs

// ---------------- scratch (no allocs allowed) ----------------
__device__ float g_wrpart[KSPL * RREL * D];
__device__ float g_wr[RREL * D];           // rela @ Wa^T
__device__ float g_agg[N_DRUG * D];
__device__ float g_hpart[KSPL * N_DRUG * D];
__device__ float g_h[N_DRUG * D];
__device__ float g_psum[NBN * D];
__device__ float g_psumsq[NBN * D];
__device__ float g_mean[D];
__device__ float g_rstd[D];
// wave schedule (computed by k_wave each call, deterministic)
__device__ int g_order[N_DRUG];
__device__ int g_wstart[N_DRUG + 2];
__device__ int g_nwaves;

// ---------------- k1: Wr partials = rela @ Wa^T [ksplit] --------------------
// out[r][e] = sum_d rela[r][d] * Wa[e][d].  BM=64 BN=64 BK=16, 4x4 tile.
__global__ void k_rgemm(const float* __restrict__ relaW,
                        const float* __restrict__ Wa) {
    __shared__ float As[2][16][68];
    __shared__ float Bs[2][16][68];
    const int tid = threadIdx.x;
    const int m0 = blockIdx.x * 64;      // r
    const int n0 = blockIdx.y * 64;      // e
    const int sp = blockIdx.z;
    const int kbase = sp * (D / KSPL);   // 128
    const int lk = tid & 15;
    const int lm = tid >> 4;
    const int bn_i = tid >> 2;           // B loader row (e)
    const int kq = (tid & 3) * 4;        // B loader k quad
    const int ty = tid >> 4, tx = tid & 15;

    float acc[4][4] = {};

    #pragma unroll
    for (int p = 0; p < 4; p++) {
        int m = lm + p * 16;
        As[0][lk][m] = (m0 + m < RREL)
                       ? relaW[(size_t)(m0 + m) * D + kbase + lk] : 0.f;
    }
    {
        float4 w = *(const float4*)&Wa[(size_t)(n0 + bn_i) * D + kbase + kq];
        Bs[0][kq + 0][bn_i] = w.x; Bs[0][kq + 1][bn_i] = w.y;
        Bs[0][kq + 2][bn_i] = w.z; Bs[0][kq + 3][bn_i] = w.w;
    }
    __syncthreads();

    int buf = 0;
    const int NCH = (D / KSPL) / 16;     // 8
    for (int ch = 0; ch < NCH; ch++) {
        float a_ld[4]; float4 b_ld;
        const bool has = (ch + 1 < NCH);
        if (has) {
            const int k1 = kbase + (ch + 1) * 16;
            #pragma unroll
            for (int p = 0; p < 4; p++) {
                int m = lm + p * 16;
                a_ld[p] = (m0 + m < RREL)
                          ? relaW[(size_t)(m0 + m) * D + k1 + lk] : 0.f;
            }
            b_ld = *(const float4*)&Wa[(size_t)(n0 + bn_i) * D + k1 + kq];
        }
        #pragma unroll
        for (int kk = 0; kk < 16; kk++) {
            float4 a = *(const float4*)&As[buf][kk][4 * ty];
            float4 b = *(const float4*)&Bs[buf][kk][4 * tx];
            acc[0][0] += a.x * b.x; acc[0][1] += a.x * b.y;
            acc[0][2] += a.x * b.z; acc[0][3] += a.x * b.w;
            acc[1][0] += a.y * b.x; acc[1][1] += a.y * b.y;
            acc[1][2] += a.y * b.z; acc[1][3] += a.y * b.w;
            acc[2][0] += a.z * b.x; acc[2][1] += a.z * b.y;
            acc[2][2] += a.z * b.z; acc[2][3] += a.z * b.w;
            acc[3][0] += a.w * b.x; acc[3][1] += a.w * b.y;
            acc[3][2] += a.w * b.z; acc[3][3] += a.w * b.w;
        }
        if (has) {
            #pragma unroll
            for (int p = 0; p < 4; p++) As[buf ^ 1][lk][lm + p * 16] = a_ld[p];
            Bs[buf ^ 1][kq + 0][bn_i] = b_ld.x;
            Bs[buf ^ 1][kq + 1][bn_i] = b_ld.y;
            Bs[buf ^ 1][kq + 2][bn_i] = b_ld.z;
            Bs[buf ^ 1][kq + 3][bn_i] = b_ld.w;
        }
        __syncthreads();
        buf ^= 1;
    }

    float* dst = g_wrpart + (size_t)sp * RREL * D;
    #pragma unroll
    for (int r = 0; r < 4; r++) {
        int row = m0 + 4 * ty + r;
        if (row < RREL) {
            float4 v = make_float4(acc[r][0], acc[r][1], acc[r][2], acc[r][3]);
            *(float4*)&dst[(size_t)row * D + n0 + 4 * tx] = v;
        }
    }
}

// ---------------- combine Wr partials ----------------
__global__ void k_wcomb() {
    const int r = blockIdx.x;
    const int d = threadIdx.x;
    float v = 0.f;
    #pragma unroll
    for (int s = 0; s < KSPL; s++)
        v += g_wrpart[(size_t)(s * RREL + r) * D + d];
    g_wr[(size_t)r * D + d] = v;
}

// ---------------- k3: h partials = concat(agg, drug_e)[ksplit] @ lin_W ------
__global__ void k_lin(const float* __restrict__ drugW,
                      const float* __restrict__ linW,
                      const int* __restrict__ names,
                      const int spbase) {
    __shared__ float As[2][16][68];
    __shared__ float Bs[2][16][68];
    __shared__ int nm[64];
    const int tid = threadIdx.x;
    const int m0 = blockIdx.x * 64;
    const int n0 = blockIdx.y * 64;
    const int sp = blockIdx.z + spbase;    // 0,1: agg halves; 2,3: drug halves
    const bool useDrug = sp >= 2;
    const int kA = (sp & 1) * 256;
    const int kB = sp * 256;
    if (tid < 64) {
        int r = m0 + tid;
        nm[tid] = r < N_DRUG ? names[r] : 0;
    }
    const int lk = tid & 15;
    const int lm = tid >> 4;
    const int bn = tid & 63;
    const int bk = tid >> 6;
    const int ty = tid >> 4, tx = tid & 15;
    __syncthreads();

    float acc[4][4] = {};

    #pragma unroll
    for (int p = 0; p < 4; p++) {
        int m = lm + p * 16;
        int row = m0 + m;
        float v = 0.f;
        if (row < N_DRUG)
            v = useDrug ? drugW[(size_t)nm[m] * D + kA + lk]
                        : g_agg[(size_t)row * D + kA + lk];
        As[0][lk][m] = v;
    }
    #pragma unroll
    for (int p = 0; p < 4; p++) {
        int kk = bk + p * 4;
        Bs[0][kk][bn] = linW[(size_t)(kB + kk) * D + n0 + bn];
    }
    __syncthreads();

    int buf = 0;
    const int NCH = 256 / 16;      // 16
    for (int ch = 0; ch < NCH; ch++) {
        float a_ld[4], b_ld[4];
        const bool has = (ch + 1 < NCH);
        if (has) {
            const int kl = kA + (ch + 1) * 16 + lk;
            #pragma unroll
            for (int p = 0; p < 4; p++) {
                int m = lm + p * 16;
                int row = m0 + m;
                float v = 0.f;
                if (row < N_DRUG)
                    v = useDrug ? drugW[(size_t)nm[m] * D + kl]
                                : g_agg[(size_t)row * D + kl];
                a_ld[p] = v;
            }
            const int kg = kB + (ch + 1) * 16;
            #pragma unroll
            for (int p = 0; p < 4; p++) {
                int kk = bk + p * 4;
                b_ld[p] = linW[(size_t)(kg + kk) * D + n0 + bn];
            }
        }
        #pragma unroll
        for (int kk = 0; kk < 16; kk++) {
            float4 a = *(const float4*)&As[buf][kk][4 * ty];
            float4 b = *(const float4*)&Bs[buf][kk][4 * tx];
            acc[0][0] += a.x * b.x; acc[0][1] += a.x * b.y;
            acc[0][2] += a.x * b.z; acc[0][3] += a.x * b.w;
            acc[1][0] += a.y * b.x; acc[1][1] += a.y * b.y;
            acc[1][2] += a.y * b.z; acc[1][3] += a.y * b.w;
            acc[2][0] += a.z * b.x; acc[2][1] += a.z * b.y;
            acc[2][2] += a.z * b.z; acc[2][3] += a.z * b.w;
            acc[3][0] += a.w * b.x; acc[3][1] += a.w * b.y;
            acc[3][2] += a.w * b.z; acc[3][3] += a.w * b.w;
        }
        if (has) {
            #pragma unroll
            for (int p = 0; p < 4; p++) As[buf ^ 1][lk][lm + p * 16] = a_ld[p];
            #pragma unroll
            for (int p = 0; p < 4; p++) Bs[buf ^ 1][bk + p * 4][bn] = b_ld[p];
        }
        __syncthreads();
        buf ^= 1;
    }

    float* dst = g_hpart + (size_t)sp * N_DRUG * D;
    #pragma unroll
    for (int r = 0; r < 4; r++) {
        int row = m0 + 4 * ty + r;
        if (row < N_DRUG) {
            float4 v = make_float4(acc[r][0], acc[r][1], acc[r][2], acc[r][3]);
            *(float4*)&dst[(size_t)row * D + n0 + 4 * tx] = v;
        }
    }
}

// ---------------- k2: attention + softmax + gather-aggregate ----------------
// scores[n][k] = drug_e[n] . Wr[rel[n][k]]   (Wr = rela @ Wa^T, precomputed)
__global__ void k_attn(const float* __restrict__ drugW,
                       const float* __restrict__ entW,
                       const int* __restrict__ adjR,
                       const int* __restrict__ adjT,
                       const int* __restrict__ names) {
    const int n = blockIdx.x;
    const int tid = threadIdx.x;           // 256 threads
    __shared__ float qsh[D];
    __shared__ float sc[KNBR];
    __shared__ float attn[KNBR];
    __shared__ int relS[KNBR], tailS[KNBR];

    if (tid < KNBR) {
        relS[tid]  = adjR[n * KNBR + tid];
        tailS[tid] = adjT[n * KNBR + tid];
    }
    const int nmrow = __ldg(&names[n]);
    qsh[tid]       = drugW[(size_t)nmrow * D + tid];
    qsh[tid + 256] = drugW[(size_t)nmrow * D + tid + 256];
    __syncthreads();

    const int w = tid >> 5, lane = tid & 31;
    #pragma unroll
    for (int kk = 0; kk < 8; kk++) {
        int k = w * 8 + kk;
        const float* base = g_wr + (size_t)relS[k] * D;
        float p = 0.f;
        #pragma unroll
        for (int i = 0; i < 16; i++)
            p += qsh[lane + 32 * i] * base[lane + 32 * i];
        #pragma unroll
        for (int off = 16; off; off >>= 1)
            p += __shfl_xor_sync(0xffffffffu, p, off);
        if (lane == 0) sc[k] = p * 0.044194173824159216f;  // 1/sqrt(512)
    }
    __syncthreads();

    if (w == 0) {
        float v0 = sc[lane], v1 = sc[lane + 32];
        float m = fmaxf(v0, v1);
        #pragma unroll
        for (int off = 16; off; off >>= 1)
            m = fmaxf(m, __shfl_xor_sync(0xffffffffu, m, off));
        float e0 = expf(v0 - m), e1 = expf(v1 - m);
        float s = e0 + e1;
        #pragma unroll
        for (int off = 16; off; off >>= 1)
            s += __shfl_xor_sync(0xffffffffu, s, off);
        float inv = 1.f / s;
        attn[lane] = e0 * inv;
        attn[lane + 32] = e1 * inv;
    }
    __syncthreads();

    float a0 = 0.f, a1 = 0.f;
    const int d = tid;
    #pragma unroll 8
    for (int k = 0; k < KNBR; k++) {
        const float* er = entW + (size_t)tailS[k] * D;
        float a = attn[k];
        a0 += a * er[d];
        a1 += a * er[d + 256];
    }
    g_agg[(size_t)n * D + d]       = a0;
    g_agg[(size_t)n * D + d + 256] = a1;
}

// ---------------- k4: combine lin partials + bias + relu + BN stats ---------
__global__ void k_bnpart(const float* __restrict__ linb) {
    const int b = blockIdx.x;       // 64 blocks
    const int d = threadIdx.x;      // 512 threads
    const int r0 = b * 9;
    const int r1 = min(N_DRUG, r0 + 9);
    const float bb = linb[d];
    float s = 0.f, sq = 0.f;
    for (int r = r0; r < r1; r++) {
        float v = bb;
        #pragma unroll
        for (int sp = 0; sp < KSPL; sp++)
            v += g_hpart[(size_t)(sp * N_DRUG + r) * D + d];
        v = v > 0.f ? v : 0.f;
        g_h[(size_t)r * D + d] = v;
        s += v;
        sq += v * v;
    }
    g_psum[b * D + d] = s;
    g_psumsq[b * D + d] = sq;
}

__global__ void k_bnfin() {
    const int d = threadIdx.x;
    float s = 0.f, sq = 0.f;
    #pragma unroll
    for (int b = 0; b < NBN; b++) {
        s  += g_psum[b * D + d];
        sq += g_psumsq[b * D + d];
    }
    const float invN = 1.f / (float)N_DRUG;
    float mean = s * invN;
    float var = sq * invN - mean * mean;
    g_mean[d] = mean;
    g_rstd[d] = rsqrtf(var + EPS);
}

// ---------------- k_wave: topological wave schedule (Kahn BFS) --------------
#define WAVE_SMEM ((N_DRUG * 4 + (N_DRUG + 1) + (N_DRUG + 2) \
                   + N_DRUG * MAXDEG + 4) * 4)

__global__ void k_wave(const int* __restrict__ nbrI,
                       const int* __restrict__ nbrD,
                       const int* __restrict__ epoch) {
    if (epoch[0] <= 1) return;
    extern __shared__ int ws[];
    int* indeg  = ws;
    int* scnt   = indeg + N_DRUG;
    int* cur    = scnt + N_DRUG;
    int* order  = cur + N_DRUG;
    int* soff   = order + N_DRUG;
    int* wstart = soff + N_DRUG + 1;
    int* succ   = wstart + N_DRUG + 2;
    int* counters = succ + N_DRUG * MAXDEG;

    const int tid = threadIdx.x;               // 512
    const int wid = tid >> 5, lane = tid & 31;

    for (int i = tid; i < N_DRUG; i += 512) { indeg[i] = 0; scnt[i] = 0; }
    if (tid == 0) counters[0] = 0;
    __syncthreads();

    for (int i = tid; i < N_DRUG; i += 512) {
        int dg = nbrD[i];
        int cnt = 0;
        for (int j = 0; j < dg; j++) {
            int p = nbrI[i * MAXDEG + j];
            if (p < i) { cnt++; atomicAdd(&scnt[p], 1); }
        }
        indeg[i] = cnt;
    }
    __syncthreads();

    if (wid == 0) {
        const int CH = 18;
        int lo = lane * CH, hi = min(N_DRUG, lo + CH);
        int s = 0;
        for (int k = lo; k < hi; k++) s += scnt[k];
        int v = s;
        #pragma unroll
        for (int off = 1; off < 32; off <<= 1) {
            int t = __shfl_up_sync(0xffffffffu, v, off);
            if (lane >= off) v += t;
        }
        int excl = v - s;
        int run = excl;
        for (int k = lo; k < hi; k++) {
            soff[k] = run; cur[k] = run; run += scnt[k];
        }
        if (lane == 31) soff[N_DRUG] = run;
    }
    __syncthreads();

    for (int i = tid; i < N_DRUG; i += 512) {
        int dg = nbrD[i];
        for (int j = 0; j < dg; j++) {
            int p = nbrI[i * MAXDEG + j];
            if (p < i) {
                int pos = atomicAdd(&cur[p], 1);
                succ[pos] = i;
            }
        }
    }
    __syncthreads();

    for (int i = tid; i < N_DRUG; i += 512)
        if (indeg[i] == 0) {
            int pos = atomicAdd(&counters[0], 1);
            order[pos] = i;
        }
    __syncthreads();

    int wbase = 0;
    int placed = counters[0];
    int wcount = placed;
    int w = 0;
    if (tid == 0) { wstart[0] = 0; wstart[1] = placed; }
    __syncthreads();

    while (placed < N_DRUG && wcount > 0) {
        for (int slot = wbase + wid; slot < wbase + wcount; slot += 16) {
            int n = order[slot];
            int s0 = soff[n], s1 = soff[n + 1];
            for (int e = s0 + lane; e < s1; e += 32) {
                int sn = succ[e];
                if (atomicSub(&indeg[sn], 1) == 1) {
                    int pos = atomicAdd(&counters[0], 1);
                    order[pos] = sn;
                }
            }
        }
        __syncthreads();
        wbase += wcount;
        int total = counters[0];
        wcount = total - placed;
        placed = total;
        w++;
        if (tid == 0) wstart[w + 1] = total;
        __syncthreads();
    }

    const int nwaves = w + 1;
    for (int i = tid; i < N_DRUG; i += 512) g_order[i] = order[i];
    for (int i = tid; i <= nwaves; i += 512) g_wstart[i] = wstart[i];
    if (tid == 0) g_nwaves = nwaves;
}

// ------ k7: fused batchnorm-apply + wave-parallel neighbor smoothing --------
// Load phase applies (h-mean)*rstd*gamma+beta (per-thread column constants),
// then runs waves if epoch>1, else passes normalized values straight to out.
#define SC_NEWOFF (573 * 32)
#define SC_DUMMY  (N_DRUG * 32)
#define SCAN_SMEM ((573 * 32 + N_DRUG * 32 + N_DRUG * 32 + 2 * N_DRUG \
                    + N_DRUG + (N_DRUG + 2)) * 4)

__global__ void k_scan(float* __restrict__ out,
                       const int* __restrict__ nbrI,
                       const int* __restrict__ nbrD,
                       const int* __restrict__ epoch,
                       const float* __restrict__ gamma,
                       const float* __restrict__ beta) {
    extern __shared__ __align__(16) char dyn[];
    float* fsh  = (float*)dyn;                         // old[573*32] ++ new[572*32]
    int*   idxS = (int*)(dyn + (573 * 32 + N_DRUG * 32) * 4);
    float* sc0  = (float*)((char*)idxS + N_DRUG * 32 * 4);
    float* sc1  = sc0 + N_DRUG;
    int*   orderS  = (int*)(sc1 + N_DRUG);
    int*   wstartS = orderS + N_DRUG;

    const int tid = threadIdx.x;               // 256
    const int cbase = blockIdx.x * 32;
    const bool doScan = epoch[0] > 1;

    // normalized load: column constants are per-thread invariant (stride 256)
    {
        const int c = cbase + (tid & 31);
        const float scale = g_rstd[c] * gamma[c];
        const float shift = beta[c] - g_mean[c] * scale;
        for (int idx = tid; idx < N_DRUG * 32; idx += 256) {
            int r = idx >> 5;
            fsh[idx] = g_h[(size_t)r * D + c] * scale + shift;
        }
    }

    if (doScan) {
        if (tid < 32) fsh[SC_DUMMY + tid] = 0.f;
        for (int idx = tid; idx < N_DRUG * 32; idx += 256) {
            int r = idx >> 5, j = idx & 31;
            int dg = __ldg(&nbrD[r]);
            int p  = __ldg(&nbrI[idx]);
            int off;
            if (j < dg) off = (p << 5) + (p < r ? SC_NEWOFF : 0);
            else        off = SC_DUMMY;
            idxS[idx] = off;
        }
        for (int i = tid; i < N_DRUG; i += 256) {
            int dg = nbrD[i];
            sc0[i] = dg > 0 ? 0.5f : 1.0f;
            sc1[i] = dg > 0 ? 0.5f / (float)dg : 0.0f;
            orderS[i] = g_order[i];
        }
        const int nw = g_nwaves;
        for (int i = tid; i <= nw; i += 256) wstartS[i] = g_wstart[i];
        __syncthreads();

        const int wid = tid >> 5, lane = tid & 31;
        for (int w = 0; w < nw; w++) {
            const int s = wstartS[w], e = wstartS[w + 1];
            for (int slot = s + wid; slot < e; slot += 8) {
                const int i = orderS[slot];
                const int4* io4 = (const int4*)(idxS + (i << 5));
                float a0 = 0.f, a1 = 0.f, a2 = 0.f, a3 = 0.f;
                #pragma unroll
                for (int q = 0; q < 8; q++) {
                    int4 cc = io4[q];
                    a0 += fsh[cc.x + lane];
                    a1 += fsh[cc.y + lane];
                    a2 += fsh[cc.z + lane];
                    a3 += fsh[cc.w + lane];
                }
                float sm = (a0 + a1) + (a2 + a3);
                const int fi = (i << 5) + lane;
                fsh[SC_NEWOFF + fi] = sm * sc1[i] + fsh[fi] * sc0[i];
            }
            __syncthreads();
        }
    } else {
        __syncthreads();
    }

    const float* src = doScan ? (fsh + SC_NEWOFF) : fsh;
    const int c = cbase + (tid & 31);
    for (int idx = tid; idx < N_DRUG * 32; idx += 256) {
        int r = idx >> 5;
        out[(size_t)r * D + c] = src[idx];
    }
}

// ---------------- launch ----------------
extern "C" void kernel_launch(void* const* d_in, const int* in_sizes, int n_in,
                              void* d_out, int out_size) {
    const float* drugW = (const float*)d_in[0];
    const float* relaW = (const float*)d_in[1];
    const float* entW  = (const float*)d_in[2];
    const float* Wa    = (const float*)d_in[3];
    const float* linW  = (const float*)d_in[4];
    const float* linb  = (const float*)d_in[5];
    const float* gamma = (const float*)d_in[6];
    const float* beta  = (const float*)d_in[7];
    const int* names   = (const int*)d_in[8];
    const int* adjT    = (const int*)d_in[9];
    const int* adjR    = (const int*)d_in[10];
    const int* nbrI    = (const int*)d_in[11];
    const int* nbrD    = (const int*)d_in[12];
    const int* epoch   = (const int*)d_in[13];
    float* out = (float*)d_out;

    static cudaStream_t sB = nullptr;
    static cudaEvent_t eF = nullptr, eJ = nullptr;
    if (sB == nullptr) {
        cudaStreamCreateWithFlags(&sB, cudaStreamNonBlocking);
        cudaEventCreateWithFlags(&eF, cudaEventDisableTiming);
        cudaEventCreateWithFlags(&eJ, cudaEventDisableTiming);
        cudaFuncSetAttribute(k_scan, cudaFuncAttributeMaxDynamicSharedMemorySize,
                             SCAN_SMEM);
        cudaFuncSetAttribute(k_wave, cudaFuncAttributeMaxDynamicSharedMemorySize,
                             WAVE_SMEM);
    }

    // fork side stream off the capture-origin stream
    cudaEventRecord(eF, 0);
    cudaStreamWaitEvent(sB, eF, 0);

    // side stream: drug-half of lin (independent of agg) + wave schedule
    k_lin<<<dim3(9, 8, 2), 256, 0, sB>>>(drugW, linW, names, 2);
    k_wave<<<1, 512, WAVE_SMEM, sB>>>(nbrI, nbrD, epoch);

    // main stream: Wr GEMM -> attention -> agg-half of lin
    k_rgemm<<<dim3(4, 8, KSPL), 256>>>(relaW, Wa);
    k_wcomb<<<RREL, D>>>();
    k_attn<<<N_DRUG, 256>>>(drugW, entW, adjR, adjT, names);
    k_lin<<<dim3(9, 8, 2), 256>>>(drugW, linW, names, 0);

    // join
    cudaEventRecord(eJ, sB);
    cudaStreamWaitEvent(0, eJ, 0);

    k_bnpart<<<NBN, D>>>(linb);
    k_bnfin<<<1, D>>>();
    k_scan<<<16, 256, SCAN_SMEM>>>(out, nbrI, nbrD, epoch, gamma, beta);
}

// round 12
// speedup vs baseline: 4.6636x; 1.0466x over previous
#include <cuda_runtime.h>
#include <math.h>

#define N_DRUG 572
#define D 512
#define KNBR 64
#define RREL 200
#define MAXDEG 32
#define EPS 1e-5f
#define NBN 64   // bn partial blocks
#define KSPL 4   // K splits for GEMMs

// ---------------- scratch (no allocs allowed) ----------------
__device__ float g_wrpart[KSPL * RREL * D];
__device__ float g_wr[RREL * D];           // rela @ Wa^T
__device__ float g_agg[N_DRUG * D];
__device__ float g_hpart[KSPL * N_DRUG * D];
__device__ float g_h[N_DRUG * D];
__device__ float g_psum[NBN * D];
__device__ float g_psumsq[NBN * D];
// wave schedule (computed by k_wave each call, deterministic)
__device__ int g_order[N_DRUG];
__device__ int g_wstart[N_DRUG + 2];
__device__ int g_nwaves;

// ---------------- k1: Wr partials = rela @ Wa^T [ksplit] --------------------
__global__ void k_rgemm(const float* __restrict__ relaW,
                        const float* __restrict__ Wa) {
    __shared__ float As[2][16][68];
    __shared__ float Bs[2][16][68];
    const int tid = threadIdx.x;
    const int m0 = blockIdx.x * 64;      // r
    const int n0 = blockIdx.y * 64;      // e
    const int sp = blockIdx.z;
    const int kbase = sp * (D / KSPL);   // 128
    const int lk = tid & 15;
    const int lm = tid >> 4;
    const int bn_i = tid >> 2;           // B loader row (e)
    const int kq = (tid & 3) * 4;        // B loader k quad
    const int ty = tid >> 4, tx = tid & 15;

    float acc[4][4] = {};

    #pragma unroll
    for (int p = 0; p < 4; p++) {
        int m = lm + p * 16;
        As[0][lk][m] = (m0 + m < RREL)
                       ? relaW[(size_t)(m0 + m) * D + kbase + lk] : 0.f;
    }
    {
        float4 w = *(const float4*)&Wa[(size_t)(n0 + bn_i) * D + kbase + kq];
        Bs[0][kq + 0][bn_i] = w.x; Bs[0][kq + 1][bn_i] = w.y;
        Bs[0][kq + 2][bn_i] = w.z; Bs[0][kq + 3][bn_i] = w.w;
    }
    __syncthreads();

    int buf = 0;
    const int NCH = (D / KSPL) / 16;     // 8
    for (int ch = 0; ch < NCH; ch++) {
        float a_ld[4]; float4 b_ld;
        const bool has = (ch + 1 < NCH);
        if (has) {
            const int k1 = kbase + (ch + 1) * 16;
            #pragma unroll
            for (int p = 0; p < 4; p++) {
                int m = lm + p * 16;
                a_ld[p] = (m0 + m < RREL)
                          ? relaW[(size_t)(m0 + m) * D + k1 + lk] : 0.f;
            }
            b_ld = *(const float4*)&Wa[(size_t)(n0 + bn_i) * D + k1 + kq];
        }
        #pragma unroll
        for (int kk = 0; kk < 16; kk++) {
            float4 a = *(const float4*)&As[buf][kk][4 * ty];
            float4 b = *(const float4*)&Bs[buf][kk][4 * tx];
            acc[0][0] += a.x * b.x; acc[0][1] += a.x * b.y;
            acc[0][2] += a.x * b.z; acc[0][3] += a.x * b.w;
            acc[1][0] += a.y * b.x; acc[1][1] += a.y * b.y;
            acc[1][2] += a.y * b.z; acc[1][3] += a.y * b.w;
            acc[2][0] += a.z * b.x; acc[2][1] += a.z * b.y;
            acc[2][2] += a.z * b.z; acc[2][3] += a.z * b.w;
            acc[3][0] += a.w * b.x; acc[3][1] += a.w * b.y;
            acc[3][2] += a.w * b.z; acc[3][3] += a.w * b.w;
        }
        if (has) {
            #pragma unroll
            for (int p = 0; p < 4; p++) As[buf ^ 1][lk][lm + p * 16] = a_ld[p];
            Bs[buf ^ 1][kq + 0][bn_i] = b_ld.x;
            Bs[buf ^ 1][kq + 1][bn_i] = b_ld.y;
            Bs[buf ^ 1][kq + 2][bn_i] = b_ld.z;
            Bs[buf ^ 1][kq + 3][bn_i] = b_ld.w;
        }
        __syncthreads();
        buf ^= 1;
    }

    float* dst = g_wrpart + (size_t)sp * RREL * D;
    #pragma unroll
    for (int r = 0; r < 4; r++) {
        int row = m0 + 4 * ty + r;
        if (row < RREL) {
            float4 v = make_float4(acc[r][0], acc[r][1], acc[r][2], acc[r][3]);
            *(float4*)&dst[(size_t)row * D + n0 + 4 * tx] = v;
        }
    }
}

// ---------------- combine Wr partials (float4, high MLP) ----------------
__global__ void k_wcomb() {
    const int r = blockIdx.x;
    const int d4 = threadIdx.x;          // 128 threads, float4 each
    const float4* p0 = (const float4*)(g_wrpart + (size_t)r * D);
    const float4* p1 = (const float4*)(g_wrpart + (size_t)(RREL + r) * D);
    const float4* p2 = (const float4*)(g_wrpart + (size_t)(2 * RREL + r) * D);
    const float4* p3 = (const float4*)(g_wrpart + (size_t)(3 * RREL + r) * D);
    float4 a = p0[d4], b = p1[d4], c = p2[d4], e = p3[d4];
    float4 v;
    v.x = (a.x + b.x) + (c.x + e.x);
    v.y = (a.y + b.y) + (c.y + e.y);
    v.z = (a.z + b.z) + (c.z + e.z);
    v.w = (a.w + b.w) + (c.w + e.w);
    ((float4*)(g_wr + (size_t)r * D))[d4] = v;
}

// ---------------- k3: h partials = concat(agg, drug_e)[ksplit] @ lin_W ------
__global__ void k_lin(const float* __restrict__ drugW,
                      const float* __restrict__ linW,
                      const int* __restrict__ names,
                      const int spbase) {
    __shared__ float As[2][16][68];
    __shared__ float Bs[2][16][68];
    __shared__ int nm[64];
    const int tid = threadIdx.x;
    const int m0 = blockIdx.x * 64;
    const int n0 = blockIdx.y * 64;
    const int sp = blockIdx.z + spbase;    // 0,1: agg halves; 2,3: drug halves
    const bool useDrug = sp >= 2;
    const int kA = (sp & 1) * 256;
    const int kB = sp * 256;
    if (tid < 64) {
        int r = m0 + tid;
        nm[tid] = r < N_DRUG ? names[r] : 0;
    }
    const int lk = tid & 15;
    const int lm = tid >> 4;
    const int bn = tid & 63;
    const int bk = tid >> 6;
    const int ty = tid >> 4, tx = tid & 15;
    __syncthreads();

    float acc[4][4] = {};

    #pragma unroll
    for (int p = 0; p < 4; p++) {
        int m = lm + p * 16;
        int row = m0 + m;
        float v = 0.f;
        if (row < N_DRUG)
            v = useDrug ? drugW[(size_t)nm[m] * D + kA + lk]
                        : g_agg[(size_t)row * D + kA + lk];
        As[0][lk][m] = v;
    }
    #pragma unroll
    for (int p = 0; p < 4; p++) {
        int kk = bk + p * 4;
        Bs[0][kk][bn] = linW[(size_t)(kB + kk) * D + n0 + bn];
    }
    __syncthreads();

    int buf = 0;
    const int NCH = 256 / 16;      // 16
    for (int ch = 0; ch < NCH; ch++) {
        float a_ld[4], b_ld[4];
        const bool has = (ch + 1 < NCH);
        if (has) {
            const int kl = kA + (ch + 1) * 16 + lk;
            #pragma unroll
            for (int p = 0; p < 4; p++) {
                int m = lm + p * 16;
                int row = m0 + m;
                float v = 0.f;
                if (row < N_DRUG)
                    v = useDrug ? drugW[(size_t)nm[m] * D + kl]
                                : g_agg[(size_t)row * D + kl];
                a_ld[p] = v;
            }
            const int kg = kB + (ch + 1) * 16;
            #pragma unroll
            for (int p = 0; p < 4; p++) {
                int kk = bk + p * 4;
                b_ld[p] = linW[(size_t)(kg + kk) * D + n0 + bn];
            }
        }
        #pragma unroll
        for (int kk = 0; kk < 16; kk++) {
            float4 a = *(const float4*)&As[buf][kk][4 * ty];
            float4 b = *(const float4*)&Bs[buf][kk][4 * tx];
            acc[0][0] += a.x * b.x; acc[0][1] += a.x * b.y;
            acc[0][2] += a.x * b.z; acc[0][3] += a.x * b.w;
            acc[1][0] += a.y * b.x; acc[1][1] += a.y * b.y;
            acc[1][2] += a.y * b.z; acc[1][3] += a.y * b.w;
            acc[2][0] += a.z * b.x; acc[2][1] += a.z * b.y;
            acc[2][2] += a.z * b.z; acc[2][3] += a.z * b.w;
            acc[3][0] += a.w * b.x; acc[3][1] += a.w * b.y;
            acc[3][2] += a.w * b.z; acc[3][3] += a.w * b.w;
        }
        if (has) {
            #pragma unroll
            for (int p = 0; p < 4; p++) As[buf ^ 1][lk][lm + p * 16] = a_ld[p];
            #pragma unroll
            for (int p = 0; p < 4; p++) Bs[buf ^ 1][bk + p * 4][bn] = b_ld[p];
        }
        __syncthreads();
        buf ^= 1;
    }

    float* dst = g_hpart + (size_t)sp * N_DRUG * D;
    #pragma unroll
    for (int r = 0; r < 4; r++) {
        int row = m0 + 4 * ty + r;
        if (row < N_DRUG) {
            float4 v = make_float4(acc[r][0], acc[r][1], acc[r][2], acc[r][3]);
            *(float4*)&dst[(size_t)row * D + n0 + 4 * tx] = v;
        }
    }
}

// ---------------- k2: attention + softmax + gather-aggregate ----------------
__global__ void k_attn(const float* __restrict__ drugW,
                       const float* __restrict__ entW,
                       const int* __restrict__ adjR,
                       const int* __restrict__ adjT,
                       const int* __restrict__ names) {
    const int n = blockIdx.x;
    const int tid = threadIdx.x;           // 256 threads
    __shared__ float qsh[D];
    __shared__ float sc[KNBR];
    __shared__ float attn[KNBR];
    __shared__ int relS[KNBR], tailS[KNBR];

    if (tid < KNBR) {
        relS[tid]  = adjR[n * KNBR + tid];
        tailS[tid] = adjT[n * KNBR + tid];
    }
    const int nmrow = __ldg(&names[n]);
    qsh[tid]       = drugW[(size_t)nmrow * D + tid];
    qsh[tid + 256] = drugW[(size_t)nmrow * D + tid + 256];
    __syncthreads();

    const int w = tid >> 5, lane = tid & 31;
    #pragma unroll
    for (int kk = 0; kk < 8; kk++) {
        int k = w * 8 + kk;
        const float* base = g_wr + (size_t)relS[k] * D;
        float p = 0.f;
        #pragma unroll
        for (int i = 0; i < 16; i++)
            p += qsh[lane + 32 * i] * base[lane + 32 * i];
        #pragma unroll
        for (int off = 16; off; off >>= 1)
            p += __shfl_xor_sync(0xffffffffu, p, off);
        if (lane == 0) sc[k] = p * 0.044194173824159216f;  // 1/sqrt(512)
    }
    __syncthreads();

    if (w == 0) {
        float v0 = sc[lane], v1 = sc[lane + 32];
        float m = fmaxf(v0, v1);
        #pragma unroll
        for (int off = 16; off; off >>= 1)
            m = fmaxf(m, __shfl_xor_sync(0xffffffffu, m, off));
        float e0 = expf(v0 - m), e1 = expf(v1 - m);
        float s = e0 + e1;
        #pragma unroll
        for (int off = 16; off; off >>= 1)
            s += __shfl_xor_sync(0xffffffffu, s, off);
        float inv = 1.f / s;
        attn[lane] = e0 * inv;
        attn[lane + 32] = e1 * inv;
    }
    __syncthreads();

    float a0 = 0.f, a1 = 0.f;
    const int d = tid;
    #pragma unroll 8
    for (int k = 0; k < KNBR; k++) {
        const float* er = entW + (size_t)tailS[k] * D;
        float a = attn[k];
        a0 += a * er[d];
        a1 += a * er[d + 256];
    }
    g_agg[(size_t)n * D + d]       = a0;
    g_agg[(size_t)n * D + d + 256] = a1;
}

// ---------------- k4: combine lin partials + bias + relu + BN stats ---------
// grid (NBN, 2): y splits columns for 2x block count (latency hiding)
__global__ void k_bnpart(const float* __restrict__ linb) {
    const int b = blockIdx.x;       // 64 row-slices
    const int d = blockIdx.y * 256 + threadIdx.x;
    const int r0 = b * 9;
    const int r1 = min(N_DRUG, r0 + 9);
    const float bb = linb[d];
    float s = 0.f, sq = 0.f;
    for (int r = r0; r < r1; r++) {
        float v = bb;
        #pragma unroll
        for (int sp = 0; sp < KSPL; sp++)
            v += g_hpart[(size_t)(sp * N_DRUG + r) * D + d];
        v = v > 0.f ? v : 0.f;
        g_h[(size_t)r * D + d] = v;
        s += v;
        sq += v * v;
    }
    g_psum[b * D + d] = s;
    g_psumsq[b * D + d] = sq;
}

// ---------------- k_wave: topological wave schedule (Kahn BFS) --------------
#define WAVE_SMEM ((N_DRUG * 4 + (N_DRUG + 1) + (N_DRUG + 2) \
                   + N_DRUG * MAXDEG + 4) * 4)

__global__ void k_wave(const int* __restrict__ nbrI,
                       const int* __restrict__ nbrD,
                       const int* __restrict__ epoch) {
    if (epoch[0] <= 1) return;
    extern __shared__ int ws[];
    int* indeg  = ws;
    int* scnt   = indeg + N_DRUG;
    int* cur    = scnt + N_DRUG;
    int* order  = cur + N_DRUG;
    int* soff   = order + N_DRUG;
    int* wstart = soff + N_DRUG + 1;
    int* succ   = wstart + N_DRUG + 2;
    int* counters = succ + N_DRUG * MAXDEG;

    const int tid = threadIdx.x;               // 512
    const int wid = tid >> 5, lane = tid & 31;

    for (int i = tid; i < N_DRUG; i += 512) { indeg[i] = 0; scnt[i] = 0; }
    if (tid == 0) counters[0] = 0;
    __syncthreads();

    for (int i = tid; i < N_DRUG; i += 512) {
        int dg = nbrD[i];
        int cnt = 0;
        for (int j = 0; j < dg; j++) {
            int p = nbrI[i * MAXDEG + j];
            if (p < i) { cnt++; atomicAdd(&scnt[p], 1); }
        }
        indeg[i] = cnt;
    }
    __syncthreads();

    if (wid == 0) {
        const int CH = 18;
        int lo = lane * CH, hi = min(N_DRUG, lo + CH);
        int s = 0;
        for (int k = lo; k < hi; k++) s += scnt[k];
        int v = s;
        #pragma unroll
        for (int off = 1; off < 32; off <<= 1) {
            int t = __shfl_up_sync(0xffffffffu, v, off);
            if (lane >= off) v += t;
        }
        int excl = v - s;
        int run = excl;
        for (int k = lo; k < hi; k++) {
            soff[k] = run; cur[k] = run; run += scnt[k];
        }
        if (lane == 31) soff[N_DRUG] = run;
    }
    __syncthreads();

    for (int i = tid; i < N_DRUG; i += 512) {
        int dg = nbrD[i];
        for (int j = 0; j < dg; j++) {
            int p = nbrI[i * MAXDEG + j];
            if (p < i) {
                int pos = atomicAdd(&cur[p], 1);
                succ[pos] = i;
            }
        }
    }
    __syncthreads();

    for (int i = tid; i < N_DRUG; i += 512)
        if (indeg[i] == 0) {
            int pos = atomicAdd(&counters[0], 1);
            order[pos] = i;
        }
    __syncthreads();

    int wbase = 0;
    int placed = counters[0];
    int wcount = placed;
    int w = 0;
    if (tid == 0) { wstart[0] = 0; wstart[1] = placed; }
    __syncthreads();

    while (placed < N_DRUG && wcount > 0) {
        for (int slot = wbase + wid; slot < wbase + wcount; slot += 16) {
            int n = order[slot];
            int s0 = soff[n], s1 = soff[n + 1];
            for (int e = s0 + lane; e < s1; e += 32) {
                int sn = succ[e];
                if (atomicSub(&indeg[sn], 1) == 1) {
                    int pos = atomicAdd(&counters[0], 1);
                    order[pos] = sn;
                }
            }
        }
        __syncthreads();
        wbase += wcount;
        int total = counters[0];
        wcount = total - placed;
        placed = total;
        w++;
        if (tid == 0) wstart[w + 1] = total;
        __syncthreads();
    }

    const int nwaves = w + 1;
    for (int i = tid; i < N_DRUG; i += 512) g_order[i] = order[i];
    for (int i = tid; i <= nwaves; i += 512) g_wstart[i] = wstart[i];
    if (tid == 0) g_nwaves = nwaves;
}

// ------ k7: fused BN-finalize + BN-apply + wave-parallel smoothing ----------
// Each block first reduces the 64 BN partials for its own 32 columns
// (replaces k_bnfin), applies (h-mean)*rstd*gamma+beta during the load, then
// runs the dependency waves (epoch>1) and writes out.
#define SC_NEWOFF (573 * 32)
#define SC_DUMMY  (N_DRUG * 32)
#define SCAN_SMEM ((573 * 32 + N_DRUG * 32 + N_DRUG * 32 + 2 * N_DRUG \
                    + N_DRUG + (N_DRUG + 2)) * 4)

__global__ void k_scan(float* __restrict__ out,
                       const int* __restrict__ nbrI,
                       const int* __restrict__ nbrD,
                       const int* __restrict__ epoch,
                       const float* __restrict__ gamma,
                       const float* __restrict__ beta) {
    extern __shared__ __align__(16) char dyn[];
    float* fsh  = (float*)dyn;                         // old[573*32] ++ new[572*32]
    int*   idxS = (int*)(dyn + (573 * 32 + N_DRUG * 32) * 4);
    float* sc0  = (float*)((char*)idxS + N_DRUG * 32 * 4);
    float* sc1  = sc0 + N_DRUG;
    int*   orderS  = (int*)(sc1 + N_DRUG);
    int*   wstartS = orderS + N_DRUG;

    __shared__ float redS[8][33], redQ[8][33];
    __shared__ float scaleS[32], shiftS[32];

    const int tid = threadIdx.x;               // 256
    const int cbase = blockIdx.x * 32;
    const bool doScan = epoch[0] > 1;
    const int c32 = tid & 31, g8 = tid >> 5;

    // BN finalize for this block's 32 columns (fused bnfin)
    {
        float s = 0.f, q = 0.f;
        for (int b = g8; b < NBN; b += 8) {
            s += g_psum[b * D + cbase + c32];
            q += g_psumsq[b * D + cbase + c32];
        }
        redS[g8][c32] = s; redQ[g8][c32] = q;
    }
    __syncthreads();
    if (tid < 32) {
        float ts = 0.f, tq = 0.f;
        #pragma unroll
        for (int g = 0; g < 8; g++) { ts += redS[g][tid]; tq += redQ[g][tid]; }
        const float invN = 1.f / (float)N_DRUG;
        float mean = ts * invN;
        float var = tq * invN - mean * mean;
        float scl = rsqrtf(var + EPS) * gamma[cbase + tid];
        scaleS[tid] = scl;
        shiftS[tid] = beta[cbase + tid] - mean * scl;
    }
    __syncthreads();

    // normalized load
    {
        const int c = cbase + c32;
        const float scale = scaleS[c32];
        const float shift = shiftS[c32];
        for (int idx = tid; idx < N_DRUG * 32; idx += 256) {
            int r = idx >> 5;
            fsh[idx] = g_h[(size_t)r * D + c] * scale + shift;
        }
    }

    if (doScan) {
        if (tid < 32) fsh[SC_DUMMY + tid] = 0.f;
        for (int idx = tid; idx < N_DRUG * 32; idx += 256) {
            int r = idx >> 5, j = idx & 31;
            int dg = __ldg(&nbrD[r]);
            int p  = __ldg(&nbrI[idx]);
            int off;
            if (j < dg) off = (p << 5) + (p < r ? SC_NEWOFF : 0);
            else        off = SC_DUMMY;
            idxS[idx] = off;
        }
        for (int i = tid; i < N_DRUG; i += 256) {
            int dg = nbrD[i];
            sc0[i] = dg > 0 ? 0.5f : 1.0f;
            sc1[i] = dg > 0 ? 0.5f / (float)dg : 0.0f;
            orderS[i] = g_order[i];
        }
        const int nw = g_nwaves;
        for (int i = tid; i <= nw; i += 256) wstartS[i] = g_wstart[i];
        __syncthreads();

        const int wid = tid >> 5, lane = tid & 31;
        for (int w = 0; w < nw; w++) {
            const int s = wstartS[w], e = wstartS[w + 1];
            for (int slot = s + wid; slot < e; slot += 8) {
                const int i = orderS[slot];
                const int4* io4 = (const int4*)(idxS + (i << 5));
                float a0 = 0.f, a1 = 0.f, a2 = 0.f, a3 = 0.f;
                #pragma unroll
                for (int q = 0; q < 8; q++) {
                    int4 cc = io4[q];
                    a0 += fsh[cc.x + lane];
                    a1 += fsh[cc.y + lane];
                    a2 += fsh[cc.z + lane];
                    a3 += fsh[cc.w + lane];
                }
                float sm = (a0 + a1) + (a2 + a3);
                const int fi = (i << 5) + lane;
                fsh[SC_NEWOFF + fi] = sm * sc1[i] + fsh[fi] * sc0[i];
            }
            __syncthreads();
        }
    } else {
        __syncthreads();
    }

    const float* src = doScan ? (fsh + SC_NEWOFF) : fsh;
    const int c = cbase + c32;
    for (int idx = tid; idx < N_DRUG * 32; idx += 256) {
        int r = idx >> 5;
        out[(size_t)r * D + c] = src[idx];
    }
}

// ---------------- launch ----------------
extern "C" void kernel_launch(void* const* d_in, const int* in_sizes, int n_in,
                              void* d_out, int out_size) {
    const float* drugW = (const float*)d_in[0];
    const float* relaW = (const float*)d_in[1];
    const float* entW  = (const float*)d_in[2];
    const float* Wa    = (const float*)d_in[3];
    const float* linW  = (const float*)d_in[4];
    const float* linb  = (const float*)d_in[5];
    const float* gamma = (const float*)d_in[6];
    const float* beta  = (const float*)d_in[7];
    const int* names   = (const int*)d_in[8];
    const int* adjT    = (const int*)d_in[9];
    const int* adjR    = (const int*)d_in[10];
    const int* nbrI    = (const int*)d_in[11];
    const int* nbrD    = (const int*)d_in[12];
    const int* epoch   = (const int*)d_in[13];
    float* out = (float*)d_out;

    static cudaStream_t sB = nullptr;
    static cudaEvent_t eF = nullptr, eWr = nullptr, eJ = nullptr;
    if (sB == nullptr) {
        cudaStreamCreateWithFlags(&sB, cudaStreamNonBlocking);
        cudaEventCreateWithFlags(&eF, cudaEventDisableTiming);
        cudaEventCreateWithFlags(&eWr, cudaEventDisableTiming);
        cudaEventCreateWithFlags(&eJ, cudaEventDisableTiming);
        cudaFuncSetAttribute(k_scan, cudaFuncAttributeMaxDynamicSharedMemorySize,
                             SCAN_SMEM);
        cudaFuncSetAttribute(k_wave, cudaFuncAttributeMaxDynamicSharedMemorySize,
                             WAVE_SMEM);
    }

    // fork side stream off the capture-origin stream
    cudaEventRecord(eF, 0);
    cudaStreamWaitEvent(sB, eF, 0);

    // side stream: Wr = rela @ Wa^T (feeds attn), then wave schedule
    k_rgemm<<<dim3(4, 8, KSPL), 256, 0, sB>>>(relaW, Wa);
    k_wcomb<<<RREL, 128, 0, sB>>>();
    cudaEventRecord(eWr, sB);
    k_wave<<<1, 512, WAVE_SMEM, sB>>>(nbrI, nbrD, epoch);
    cudaEventRecord(eJ, sB);

    // main stream: drug-half of lin immediately (independent of agg)
    k_lin<<<dim3(9, 8, 2), 256>>>(drugW, linW, names, 2);
    // attn needs Wr
    cudaStreamWaitEvent(0, eWr, 0);
    k_attn<<<N_DRUG, 256>>>(drugW, entW, adjR, adjT, names);
    k_lin<<<dim3(9, 8, 2), 256>>>(drugW, linW, names, 0);
    k_bnpart<<<dim3(NBN, 2), 256>>>(linb);
    // scan needs wave schedule
    cudaStreamWaitEvent(0, eJ, 0);
    k_scan<<<16, 256, SCAN_SMEM>>>(out, nbrI, nbrD, epoch, gamma, beta);
}

// round 17
// speedup vs baseline: 5.4328x; 1.1649x over previous
#include <cuda_runtime.h>
#include <math.h>

#define N_DRUG 572
#define D 512
#define KNBR 64
#define RREL 200
#define MAXDEG 32
#define EPS 1e-5f
#define NBN 64   // bn partial blocks
#define KSPL 4   // K splits for Wr GEMM
#define HSPL 8   // total h partials (2 halves x 4 sub-splits)

// ---------------- scratch (no allocs allowed) ----------------
__device__ float g_wrpart[KSPL * RREL * D];
__device__ float g_wr[RREL * D];           // rela @ Wa^T
__device__ float g_agg[N_DRUG * D];
__device__ float g_hpart[HSPL * N_DRUG * D];
__device__ float g_h[N_DRUG * D];
__device__ float g_psum[NBN * D];
__device__ float g_psumsq[NBN * D];
// wave schedule (computed by k_wave each call, deterministic)
__device__ int g_order[N_DRUG];
__device__ int g_wstart[N_DRUG + 2];
__device__ int g_nwaves;

// ---------------- k1: Wr partials = rela @ Wa^T [ksplit] --------------------
__global__ void k_rgemm(const float* __restrict__ relaW,
                        const float* __restrict__ Wa) {
    __shared__ float As[2][16][68];
    __shared__ float Bs[2][16][68];
    const int tid = threadIdx.x;
    const int m0 = blockIdx.x * 64;      // r
    const int n0 = blockIdx.y * 64;      // e
    const int sp = blockIdx.z;
    const int kbase = sp * (D / KSPL);   // 128
    const int lk = tid & 15;
    const int lm = tid >> 4;
    const int bn_i = tid >> 2;           // B loader row (e)
    const int kq = (tid & 3) * 4;        // B loader k quad
    const int ty = tid >> 4, tx = tid & 15;

    float acc[4][4] = {};

    #pragma unroll
    for (int p = 0; p < 4; p++) {
        int m = lm + p * 16;
        As[0][lk][m] = (m0 + m < RREL)
                       ? relaW[(size_t)(m0 + m) * D + kbase + lk] : 0.f;
    }
    {
        float4 w = *(const float4*)&Wa[(size_t)(n0 + bn_i) * D + kbase + kq];
        Bs[0][kq + 0][bn_i] = w.x; Bs[0][kq + 1][bn_i] = w.y;
        Bs[0][kq + 2][bn_i] = w.z; Bs[0][kq + 3][bn_i] = w.w;
    }
    __syncthreads();

    int buf = 0;
    const int NCH = (D / KSPL) / 16;     // 8
    for (int ch = 0; ch < NCH; ch++) {
        float a_ld[4]; float4 b_ld;
        const bool has = (ch + 1 < NCH);
        if (has) {
            const int k1 = kbase + (ch + 1) * 16;
            #pragma unroll
            for (int p = 0; p < 4; p++) {
                int m = lm + p * 16;
                a_ld[p] = (m0 + m < RREL)
                          ? relaW[(size_t)(m0 + m) * D + k1 + lk] : 0.f;
            }
            b_ld = *(const float4*)&Wa[(size_t)(n0 + bn_i) * D + k1 + kq];
        }
        #pragma unroll
        for (int kk = 0; kk < 16; kk++) {
            float4 a = *(const float4*)&As[buf][kk][4 * ty];
            float4 b = *(const float4*)&Bs[buf][kk][4 * tx];
            acc[0][0] += a.x * b.x; acc[0][1] += a.x * b.y;
            acc[0][2] += a.x * b.z; acc[0][3] += a.x * b.w;
            acc[1][0] += a.y * b.x; acc[1][1] += a.y * b.y;
            acc[1][2] += a.y * b.z; acc[1][3] += a.y * b.w;
            acc[2][0] += a.z * b.x; acc[2][1] += a.z * b.y;
            acc[2][2] += a.z * b.z; acc[2][3] += a.z * b.w;
            acc[3][0] += a.w * b.x; acc[3][1] += a.w * b.y;
            acc[3][2] += a.w * b.z; acc[3][3] += a.w * b.w;
        }
        if (has) {
            #pragma unroll
            for (int p = 0; p < 4; p++) As[buf ^ 1][lk][lm + p * 16] = a_ld[p];
            Bs[buf ^ 1][kq + 0][bn_i] = b_ld.x;
            Bs[buf ^ 1][kq + 1][bn_i] = b_ld.y;
            Bs[buf ^ 1][kq + 2][bn_i] = b_ld.z;
            Bs[buf ^ 1][kq + 3][bn_i] = b_ld.w;
        }
        __syncthreads();
        buf ^= 1;
    }

    float* dst = g_wrpart + (size_t)sp * RREL * D;
    #pragma unroll
    for (int r = 0; r < 4; r++) {
        int row = m0 + 4 * ty + r;
        if (row < RREL) {
            float4 v = make_float4(acc[r][0], acc[r][1], acc[r][2], acc[r][3]);
            *(float4*)&dst[(size_t)row * D + n0 + 4 * tx] = v;
        }
    }
}

// ---------------- combine Wr partials (float4, high MLP) ----------------
__global__ void k_wcomb() {
    const int r = blockIdx.x;
    const int d4 = threadIdx.x;          // 128 threads, float4 each
    const float4* p0 = (const float4*)(g_wrpart + (size_t)r * D);
    const float4* p1 = (const float4*)(g_wrpart + (size_t)(RREL + r) * D);
    const float4* p2 = (const float4*)(g_wrpart + (size_t)(2 * RREL + r) * D);
    const float4* p3 = (const float4*)(g_wrpart + (size_t)(3 * RREL + r) * D);
    float4 a = p0[d4], b = p1[d4], c = p2[d4], e = p3[d4];
    float4 v;
    v.x = (a.x + b.x) + (c.x + e.x);
    v.y = (a.y + b.y) + (c.y + e.y);
    v.z = (a.z + b.z) + (c.z + e.z);
    v.w = (a.w + b.w) + (c.w + e.w);
    ((float4*)(g_wr + (size_t)r * D))[d4] = v;
}

// -------- k3: h partials = concat(agg, drug_e)[128-slice] @ lin_W -----------
// grid (9, 8, 4) per launch; spbase 0 = agg half, 4 = drug half.
__global__ void k_lin(const float* __restrict__ drugW,
                      const float* __restrict__ linW,
                      const int* __restrict__ names,
                      const int spbase) {
    __shared__ float As[2][16][68];
    __shared__ float Bs[2][16][68];
    __shared__ int nm[64];
    const int tid = threadIdx.x;
    const int m0 = blockIdx.x * 64;
    const int n0 = blockIdx.y * 64;
    const int sub = blockIdx.z;            // 0..3
    const int sp = spbase + sub;           // 0..7 partial index
    const bool useDrug = spbase >= 4;
    const int kA = sub * 128;              // within A source
    const int kB = sp * 128;               // within linW rows
    if (tid < 64) {
        int r = m0 + tid;
        nm[tid] = r < N_DRUG ? names[r] : 0;
    }
    const int lk = tid & 15;
    const int lm = tid >> 4;
    const int bn = tid & 63;
    const int bk = tid >> 6;
    const int ty = tid >> 4, tx = tid & 15;
    __syncthreads();

    float acc[4][4] = {};

    #pragma unroll
    for (int p = 0; p < 4; p++) {
        int m = lm + p * 16;
        int row = m0 + m;
        float v = 0.f;
        if (row < N_DRUG)
            v = useDrug ? drugW[(size_t)nm[m] * D + kA + lk]
                        : g_agg[(size_t)row * D + kA + lk];
        As[0][lk][m] = v;
    }
    #pragma unroll
    for (int p = 0; p < 4; p++) {
        int kk = bk + p * 4;
        Bs[0][kk][bn] = linW[(size_t)(kB + kk) * D + n0 + bn];
    }
    __syncthreads();

    int buf = 0;
    const int NCH = 128 / 16;      // 8
    for (int ch = 0; ch < NCH; ch++) {
        float a_ld[4], b_ld[4];
        const bool has = (ch + 1 < NCH);
        if (has) {
            const int kl = kA + (ch + 1) * 16 + lk;
            #pragma unroll
            for (int p = 0; p < 4; p++) {
                int m = lm + p * 16;
                int row = m0 + m;
                float v = 0.f;
                if (row < N_DRUG)
                    v = useDrug ? drugW[(size_t)nm[m] * D + kl]
                                : g_agg[(size_t)row * D + kl];
                a_ld[p] = v;
            }
            const int kg = kB + (ch + 1) * 16;
            #pragma unroll
            for (int p = 0; p < 4; p++) {
                int kk = bk + p * 4;
                b_ld[p] = linW[(size_t)(kg + kk) * D + n0 + bn];
            }
        }
        #pragma unroll
        for (int kk = 0; kk < 16; kk++) {
            float4 a = *(const float4*)&As[buf][kk][4 * ty];
            float4 b = *(const float4*)&Bs[buf][kk][4 * tx];
            acc[0][0] += a.x * b.x; acc[0][1] += a.x * b.y;
            acc[0][2] += a.x * b.z; acc[0][3] += a.x * b.w;
            acc[1][0] += a.y * b.x; acc[1][1] += a.y * b.y;
            acc[1][2] += a.y * b.z; acc[1][3] += a.y * b.w;
            acc[2][0] += a.z * b.x; acc[2][1] += a.z * b.y;
            acc[2][2] += a.z * b.z; acc[2][3] += a.z * b.w;
            acc[3][0] += a.w * b.x; acc[3][1] += a.w * b.y;
            acc[3][2] += a.w * b.z; acc[3][3] += a.w * b.w;
        }
        if (has) {
            #pragma unroll
            for (int p = 0; p < 4; p++) As[buf ^ 1][lk][lm + p * 16] = a_ld[p];
            #pragma unroll
            for (int p = 0; p < 4; p++) Bs[buf ^ 1][bk + p * 4][bn] = b_ld[p];
        }
        __syncthreads();
        buf ^= 1;
    }

    float* dst = g_hpart + (size_t)sp * N_DRUG * D;
    #pragma unroll
    for (int r = 0; r < 4; r++) {
        int row = m0 + 4 * ty + r;
        if (row < N_DRUG) {
            float4 v = make_float4(acc[r][0], acc[r][1], acc[r][2], acc[r][3]);
            *(float4*)&dst[(size_t)row * D + n0 + 4 * tx] = v;
        }
    }
}

// ---------------- k2: attention + softmax + gather-aggregate ----------------
__global__ void k_attn(const float* __restrict__ drugW,
                       const float* __restrict__ entW,
                       const int* __restrict__ adjR,
                       const int* __restrict__ adjT,
                       const int* __restrict__ names) {
    const int n = blockIdx.x;
    const int tid = threadIdx.x;           // 256 threads
    __shared__ float qsh[D];
    __shared__ float sc[KNBR];
    __shared__ float attn[KNBR];
    __shared__ int relS[KNBR], tailS[KNBR];

    if (tid < KNBR) {
        relS[tid]  = adjR[n * KNBR + tid];
        tailS[tid] = adjT[n * KNBR + tid];
    }
    const int nmrow = __ldg(&names[n]);
    qsh[tid]       = drugW[(size_t)nmrow * D + tid];
    qsh[tid + 256] = drugW[(size_t)nmrow * D + tid + 256];
    __syncthreads();

    const int w = tid >> 5, lane = tid & 31;
    #pragma unroll
    for (int kk = 0; kk < 8; kk++) {
        int k = w * 8 + kk;
        const float* base = g_wr + (size_t)relS[k] * D;
        float p = 0.f;
        #pragma unroll
        for (int i = 0; i < 16; i++)
            p += qsh[lane + 32 * i] * base[lane + 32 * i];
        #pragma unroll
        for (int off = 16; off; off >>= 1)
            p += __shfl_xor_sync(0xffffffffu, p, off);
        if (lane == 0) sc[k] = p * 0.044194173824159216f;  // 1/sqrt(512)
    }
    __syncthreads();

    if (w == 0) {
        float v0 = sc[lane], v1 = sc[lane + 32];
        float m = fmaxf(v0, v1);
        #pragma unroll
        for (int off = 16; off; off >>= 1)
            m = fmaxf(m, __shfl_xor_sync(0xffffffffu, m, off));
        float e0 = expf(v0 - m), e1 = expf(v1 - m);
        float s = e0 + e1;
        #pragma unroll
        for (int off = 16; off; off >>= 1)
            s += __shfl_xor_sync(0xffffffffu, s, off);
        float inv = 1.f / s;
        attn[lane] = e0 * inv;
        attn[lane + 32] = e1 * inv;
    }
    __syncthreads();

    float a0 = 0.f, a1 = 0.f;
    const int d = tid;
    #pragma unroll 8
    for (int k = 0; k < KNBR; k++) {
        const float* er = entW + (size_t)tailS[k] * D;
        float a = attn[k];
        a0 += a * er[d];
        a1 += a * er[d + 256];
    }
    g_agg[(size_t)n * D + d]       = a0;
    g_agg[(size_t)n * D + d + 256] = a1;
}

// ---------------- k4: combine lin partials + bias + relu + BN stats ---------
__global__ void k_bnpart(const float* __restrict__ linb) {
    const int b = blockIdx.x;       // 64 row-slices
    const int d = blockIdx.y * 256 + threadIdx.x;
    const int r0 = b * 9;
    const int r1 = min(N_DRUG, r0 + 9);
    const float bb = linb[d];
    float s = 0.f, sq = 0.f;
    for (int r = r0; r < r1; r++) {
        float v = bb;
        #pragma unroll
        for (int sp = 0; sp < HSPL; sp++)
            v += g_hpart[(size_t)(sp * N_DRUG + r) * D + d];
        v = v > 0.f ? v : 0.f;
        g_h[(size_t)r * D + d] = v;
        s += v;
        sq += v * v;
    }
    g_psum[b * D + d] = s;
    g_psumsq[b * D + d] = sq;
}

// ---------------- k_wave: topological wave schedule (Kahn BFS) --------------
#define WAVE_SMEM ((N_DRUG * 4 + (N_DRUG + 1) + (N_DRUG + 2) \
                   + N_DRUG * MAXDEG + 4) * 4)

__global__ void k_wave(const int* __restrict__ nbrI,
                       const int* __restrict__ nbrD,
                       const int* __restrict__ epoch) {
    if (epoch[0] <= 1) return;
    extern __shared__ int ws[];
    int* indeg  = ws;
    int* scnt   = indeg + N_DRUG;
    int* cur    = scnt + N_DRUG;
    int* order  = cur + N_DRUG;
    int* soff   = order + N_DRUG;
    int* wstart = soff + N_DRUG + 1;
    int* succ   = wstart + N_DRUG + 2;
    int* counters = succ + N_DRUG * MAXDEG;

    const int tid = threadIdx.x;               // 512
    const int wid = tid >> 5, lane = tid & 31;

    for (int i = tid; i < N_DRUG; i += 512) { indeg[i] = 0; scnt[i] = 0; }
    if (tid == 0) counters[0] = 0;
    __syncthreads();

    for (int i = tid; i < N_DRUG; i += 512) {
        int dg = nbrD[i];
        int cnt = 0;
        for (int j = 0; j < dg; j++) {
            int p = nbrI[i * MAXDEG + j];
            if (p < i) { cnt++; atomicAdd(&scnt[p], 1); }
        }
        indeg[i] = cnt;
    }
    __syncthreads();

    if (wid == 0) {
        const int CH = 18;
        int lo = lane * CH, hi = min(N_DRUG, lo + CH);
        int s = 0;
        for (int k = lo; k < hi; k++) s += scnt[k];
        int v = s;
        #pragma unroll
        for (int off = 1; off < 32; off <<= 1) {
            int t = __shfl_up_sync(0xffffffffu, v, off);
            if (lane >= off) v += t;
        }
        int excl = v - s;
        int run = excl;
        for (int k = lo; k < hi; k++) {
            soff[k] = run; cur[k] = run; run += scnt[k];
        }
        if (lane == 31) soff[N_DRUG] = run;
    }
    __syncthreads();

    for (int i = tid; i < N_DRUG; i += 512) {
        int dg = nbrD[i];
        for (int j = 0; j < dg; j++) {
            int p = nbrI[i * MAXDEG + j];
            if (p < i) {
                int pos = atomicAdd(&cur[p], 1);
                succ[pos] = i;
            }
        }
    }
    __syncthreads();

    for (int i = tid; i < N_DRUG; i += 512)
        if (indeg[i] == 0) {
            int pos = atomicAdd(&counters[0], 1);
            order[pos] = i;
        }
    __syncthreads();

    int wbase = 0;
    int placed = counters[0];
    int wcount = placed;
    int w = 0;
    if (tid == 0) { wstart[0] = 0; wstart[1] = placed; }
    __syncthreads();

    while (placed < N_DRUG && wcount > 0) {
        for (int slot = wbase + wid; slot < wbase + wcount; slot += 16) {
            int n = order[slot];
            int s0 = soff[n], s1 = soff[n + 1];
            for (int e = s0 + lane; e < s1; e += 32) {
                int sn = succ[e];
                if (atomicSub(&indeg[sn], 1) == 1) {
                    int pos = atomicAdd(&counters[0], 1);
                    order[pos] = sn;
                }
            }
        }
        __syncthreads();
        wbase += wcount;
        int total = counters[0];
        wcount = total - placed;
        placed = total;
        w++;
        if (tid == 0) wstart[w + 1] = total;
        __syncthreads();
    }

    const int nwaves = w + 1;
    for (int i = tid; i < N_DRUG; i += 512) g_order[i] = order[i];
    for (int i = tid; i <= nwaves; i += 512) g_wstart[i] = wstart[i];
    if (tid == 0) g_nwaves = nwaves;
}

// ------ k7: fused BN-finalize + BN-apply + wave-parallel smoothing ----------
// 512 threads: 16 warps -> 16 nodes/wave. BN reduce uses only 8 groups
// (tid<256) to keep static smem small: dynamic 228936 + static ~2.4KB < 227KB cap.
#define SC_NEWOFF (573 * 32)
#define SC_DUMMY  (N_DRUG * 32)
#define SCAN_SMEM ((573 * 32 + N_DRUG * 32 + N_DRUG * 32 + 2 * N_DRUG \
                    + N_DRUG + (N_DRUG + 2)) * 4)

__global__ void k_scan(float* __restrict__ out,
                       const int* __restrict__ nbrI,
                       const int* __restrict__ nbrD,
                       const int* __restrict__ epoch,
                       const float* __restrict__ gamma,
                       const float* __restrict__ beta) {
    extern __shared__ __align__(16) char dyn[];
    float* fsh  = (float*)dyn;                         // old[573*32] ++ new[572*32]
    int*   idxS = (int*)(dyn + (573 * 32 + N_DRUG * 32) * 4);
    float* sc0  = (float*)((char*)idxS + N_DRUG * 32 * 4);
    float* sc1  = sc0 + N_DRUG;
    int*   orderS  = (int*)(sc1 + N_DRUG);
    int*   wstartS = orderS + N_DRUG;

    __shared__ float redS[8][33], redQ[8][33];
    __shared__ float scaleS[32], shiftS[32];

    const int tid = threadIdx.x;               // 512
    const int cbase = blockIdx.x * 32;
    const bool doScan = epoch[0] > 1;
    const int c32 = tid & 31;

    // BN finalize for this block's 32 columns (first 8 warps only)
    if (tid < 256) {
        const int g8 = tid >> 5;
        float s = 0.f, q = 0.f;
        for (int b = g8; b < NBN; b += 8) {
            s += g_psum[b * D + cbase + c32];
            q += g_psumsq[b * D + cbase + c32];
        }
        redS[g8][c32] = s; redQ[g8][c32] = q;
    }
    __syncthreads();
    if (tid < 32) {
        float ts = 0.f, tq = 0.f;
        #pragma unroll
        for (int g = 0; g < 8; g++) { ts += redS[g][tid]; tq += redQ[g][tid]; }
        const float invN = 1.f / (float)N_DRUG;
        float mean = ts * invN;
        float var = tq * invN - mean * mean;
        float scl = rsqrtf(var + EPS) * gamma[cbase + tid];
        scaleS[tid] = scl;
        shiftS[tid] = beta[cbase + tid] - mean * scl;
    }
    __syncthreads();

    // normalized load
    {
        const int c = cbase + c32;
        const float scale = scaleS[c32];
        const float shift = shiftS[c32];
        for (int idx = tid; idx < N_DRUG * 32; idx += 512) {
            int r = idx >> 5;
            fsh[idx] = g_h[(size_t)r * D + c] * scale + shift;
        }
    }

    if (doScan) {
        if (tid < 32) fsh[SC_DUMMY + tid] = 0.f;
        for (int idx = tid; idx < N_DRUG * 32; idx += 512) {
            int r = idx >> 5, j = idx & 31;
            int dg = __ldg(&nbrD[r]);
            int p  = __ldg(&nbrI[idx]);
            int off;
            if (j < dg) off = (p << 5) + (p < r ? SC_NEWOFF : 0);
            else        off = SC_DUMMY;
            idxS[idx] = off;
        }
        for (int i = tid; i < N_DRUG; i += 512) {
            int dg = nbrD[i];
            sc0[i] = dg > 0 ? 0.5f : 1.0f;
            sc1[i] = dg > 0 ? 0.5f / (float)dg : 0.0f;
            orderS[i] = g_order[i];
        }
        const int nw = g_nwaves;
        for (int i = tid; i <= nw; i += 512) wstartS[i] = g_wstart[i];
        __syncthreads();

        const int wid = tid >> 5, lane = tid & 31;
        for (int w = 0; w < nw; w++) {
            const int s = wstartS[w], e = wstartS[w + 1];
            for (int slot = s + wid; slot < e; slot += 16) {
                const int i = orderS[slot];
                const int4* io4 = (const int4*)(idxS + (i << 5));
                float a0 = 0.f, a1 = 0.f, a2 = 0.f, a3 = 0.f;
                #pragma unroll
                for (int q = 0; q < 8; q++) {
                    int4 cc = io4[q];
                    a0 += fsh[cc.x + lane];
                    a1 += fsh[cc.y + lane];
                    a2 += fsh[cc.z + lane];
                    a3 += fsh[cc.w + lane];
                }
                float sm = (a0 + a1) + (a2 + a3);
                const int fi = (i << 5) + lane;
                fsh[SC_NEWOFF + fi] = sm * sc1[i] + fsh[fi] * sc0[i];
            }
            __syncthreads();
        }
    } else {
        __syncthreads();
    }

    const float* src = doScan ? (fsh + SC_NEWOFF) : fsh;
    const int c = cbase + c32;
    for (int idx = tid; idx < N_DRUG * 32; idx += 512) {
        int r = idx >> 5;
        out[(size_t)r * D + c] = src[idx];
    }
}

// ---------------- launch ----------------
extern "C" void kernel_launch(void* const* d_in, const int* in_sizes, int n_in,
                              void* d_out, int out_size) {
    const float* drugW = (const float*)d_in[0];
    const float* relaW = (const float*)d_in[1];
    const float* entW  = (const float*)d_in[2];
    const float* Wa    = (const float*)d_in[3];
    const float* linW  = (const float*)d_in[4];
    const float* linb  = (const float*)d_in[5];
    const float* gamma = (const float*)d_in[6];
    const float* beta  = (const float*)d_in[7];
    const int* names   = (const int*)d_in[8];
    const int* adjT    = (const int*)d_in[9];
    const int* adjR    = (const int*)d_in[10];
    const int* nbrI    = (const int*)d_in[11];
    const int* nbrD    = (const int*)d_in[12];
    const int* epoch   = (const int*)d_in[13];
    float* out = (float*)d_out;

    static cudaStream_t sB = nullptr;
    static cudaEvent_t eF = nullptr, eWr = nullptr, eJ = nullptr;
    if (sB == nullptr) {
        cudaStreamCreateWithFlags(&sB, cudaStreamNonBlocking);
        cudaEventCreateWithFlags(&eF, cudaEventDisableTiming);
        cudaEventCreateWithFlags(&eWr, cudaEventDisableTiming);
        cudaEventCreateWithFlags(&eJ, cudaEventDisableTiming);
        cudaFuncSetAttribute(k_scan, cudaFuncAttributeMaxDynamicSharedMemorySize,
                             SCAN_SMEM);
        cudaFuncSetAttribute(k_wave, cudaFuncAttributeMaxDynamicSharedMemorySize,
                             WAVE_SMEM);
    }

    // fork side stream off the capture-origin stream
    cudaEventRecord(eF, 0);
    cudaStreamWaitEvent(sB, eF, 0);

    // side stream: Wr = rela @ Wa^T (feeds attn), then wave schedule
    k_rgemm<<<dim3(4, 8, KSPL), 256, 0, sB>>>(relaW, Wa);
    k_wcomb<<<RREL, 128, 0, sB>>>();
    cudaEventRecord(eWr, sB);
    k_wave<<<1, 512, WAVE_SMEM, sB>>>(nbrI, nbrD, epoch);
    cudaEventRecord(eJ, sB);

    // main stream: drug-half of lin immediately (independent of agg)
    k_lin<<<dim3(9, 8, 4), 256>>>(drugW, linW, names, 4);
    // attn needs Wr
    cudaStreamWaitEvent(0, eWr, 0);
    k_attn<<<N_DRUG, 256>>>(drugW, entW, adjR, adjT, names);
    k_lin<<<dim3(9, 8, 4), 256>>>(drugW, linW, names, 0);
    k_bnpart<<<dim3(NBN, 2), 256>>>(linb);
    // scan needs wave schedule
    cudaStreamWaitEvent(0, eJ, 0);
    k_scan<<<16, 512, SCAN_SMEM>>>(out, nbrI, nbrD, epoch, gamma, beta);
}